// round 2
// baseline (speedup 1.0000x reference)
#include <cuda_runtime.h>
#include <cstdint>

#define B_   2048
#define S_   512
#define DIN  5
#define H_   64
#define CC   32
#define EDIM 32
#define NEMB 64

// ---------------- static device scratch (allocation-free rule) ----------------
__device__ __align__(16) float g_convout[(size_t)S_*B_*CC];   // [S][B][32]
__device__ __align__(16) float g_xT[(size_t)S_*B_*8];         // [S][B][5] (row stride 5, padded alloc)
__device__ __align__(16) float g_ys_cnn[(size_t)S_*B_*H_];    // [S][B][64]
__device__ __align__(16) float g_ys_vq[(size_t)S_*B_*H_];     // [S][B][64]
__device__ __align__(16) float g_cnn_feat[B_*H_];
__device__ __align__(16) float g_vq_hid[B_*H_];
__device__ float g_sqsum;
__device__ int   g_counts[NEMB];

// ---------------- helpers ----------------
__device__ __forceinline__ void fma2(unsigned long long& d, unsigned long long a, unsigned long long b){
    asm("fma.rn.f32x2 %0, %1, %2, %0;" : "+l"(d) : "l"(a), "l"(b));
}
__device__ __forceinline__ unsigned long long pack2(float x, float y){
    unsigned long long r; asm("mov.b64 %0, {%1,%2};" : "=l"(r) : "f"(x), "f"(y)); return r;
}
__device__ __forceinline__ float2 unpack2(unsigned long long v){
    float2 r; asm("mov.b64 {%0,%1}, %2;" : "=f"(r.x), "=f"(r.y) : "l"(v)); return r;
}
__device__ __forceinline__ float sig_(float x){ return __fdividef(1.f, 1.f + __expf(-x)); }
__device__ __forceinline__ float tanh_(float x){ return __fdividef(2.f, 1.f + __expf(-2.f*x)) - 1.f; }

// ---------------- prep: conv1d(k=3,pad=1) + BN(eval) + ReLU, and x transpose ----------------
__global__ void prep_kernel(const float* __restrict__ x, const float* __restrict__ conv_w,
                            const float* __restrict__ conv_b, const float* __restrict__ bn_g,
                            const float* __restrict__ bn_b, const float* __restrict__ bn_m,
                            const float* __restrict__ bn_v)
{
    __shared__ float ws[CC*15];
    __shared__ float bs[CC];
    int tid = threadIdx.x;
    for (int idx = tid; idx < CC*15; idx += 256){
        int c = idx / 15;
        float sc = bn_g[c] * rsqrtf(bn_v[c] + 1e-5f);
        ws[idx] = conv_w[idx] * sc;
    }
    if (tid < CC){
        float sc = bn_g[tid] * rsqrtf(bn_v[tid] + 1e-5f);
        bs[tid] = (conv_b[tid] - bn_m[tid]) * sc + bn_b[tid];
    }
    __syncthreads();

    int gid = blockIdx.x * 256 + tid;        // gid = b*S + s
    int s = gid & (S_-1);
    int b = gid >> 9;
    size_t xb = (size_t)gid * DIN;
    float x0[DIN], xm[DIN], xp[DIN];
    #pragma unroll
    for (int i = 0; i < DIN; i++){
        x0[i] = x[xb + i];
        xm[i] = (s > 0)      ? x[xb - DIN + i] : 0.f;
        xp[i] = (s < S_-1)   ? x[xb + DIN + i] : 0.f;
    }
    float o[CC];
    #pragma unroll
    for (int c = 0; c < CC; c++){
        float acc = bs[c];
        #pragma unroll
        for (int i = 0; i < DIN; i++){
            acc = fmaf(xm[i], ws[c*15 + i*3 + 0], acc);
            acc = fmaf(x0[i], ws[c*15 + i*3 + 1], acc);
            acc = fmaf(xp[i], ws[c*15 + i*3 + 2], acc);
        }
        o[c] = fmaxf(acc, 0.f);
    }
    float4* dst = (float4*)&g_convout[((size_t)s*B_ + b)*CC];
    #pragma unroll
    for (int c = 0; c < CC/4; c++) dst[c] = make_float4(o[4*c], o[4*c+1], o[4*c+2], o[4*c+3]);
    float* xt = &g_xT[((size_t)s*B_ + b)*DIN];
    #pragma unroll
    for (int i = 0; i < DIN; i++) xt[i] = x0[i];
}

// ---------------- fused 2-stream LSTM layer kernel ----------------
// 128 CTAs: blocks [0,64) = stream A (cnn), [64,128) = stream B (vq). 32 rows/CTA.
// Weights in smem in K-PAIR layout: Wp[(k/2)*512 + 2n + (k&1)] so fma.rn.f32x2
// accumulates (even-k, odd-k) partial sums with zero pack instructions.
__global__ void __launch_bounds__(256, 1) lstm_pair(int layer,
    const float* __restrict__ wihA, const float* __restrict__ whhA,
    const float* __restrict__ bihA, const float* __restrict__ bhhA,
    const float* __restrict__ wihB, const float* __restrict__ whhB,
    const float* __restrict__ bihB, const float* __restrict__ bhhB)
{
    extern __shared__ float sm[];
    int tid = threadIdx.x;
    bool isA = blockIdx.x < 64;
    int cid = isA ? blockIdx.x : blockIdx.x - 64;

    const float *wih, *whh, *bih, *bhh, *in_seq;
    float *ys = nullptr, *hf = nullptr;
    int kin, kpad;
    if (layer == 0){
        if (isA){ in_seq = g_convout; kin = CC;  kpad = 96;  wih=wihA; whh=whhA; bih=bihA; bhh=bhhA; ys = g_ys_cnn; }
        else    { in_seq = g_xT;      kin = DIN; kpad = 72;  wih=wihB; whh=whhB; bih=bihB; bhh=bhhB; ys = g_ys_vq; }
    } else {
        if (isA){ in_seq = g_ys_cnn;  kin = H_;  kpad = 128; wih=wihA; whh=whhA; bih=bihA; bhh=bhhA; hf = g_cnn_feat; }
        else    { in_seq = g_ys_vq;   kin = H_;  kpad = 128; wih=wihB; whh=whhB; bih=bihB; bhh=bhhB; hf = g_vq_hid; }
    }

    float* Wp     = sm;                    // kpad*256 floats (pair layout)
    float* bias_s = Wp + kpad*256;         // 256
    float* inbuf  = bias_s + 256;          // 32*kpad : [x_t | h | zero-pad]
    float* gates  = inbuf + 32*kpad;       // 32*256
    float* c_s    = gates + 32*256;        // 32*64

    // one-time: load weights (transposed + k-paired), bias, zero state
    for (int idx = tid; idx < 256*kpad; idx += 256){
        int n = idx / kpad, k = idx - n*kpad;
        float v = 0.f;
        if (k < kin)            v = wih[n*kin + k];
        else if (k < kin + H_)  v = whh[n*H_ + (k - kin)];
        Wp[(k >> 1)*512 + (n << 1) + (k & 1)] = v;
    }
    bias_s[tid] = bih[tid] + bhh[tid];
    for (int idx = tid; idx < 32*kpad; idx += 256) inbuf[idx] = 0.f;
    for (int idx = tid; idx < 32*H_;   idx += 256) c_s[idx]   = 0.f;
    __syncthreads();

    const int cg = tid & 63, rg = tid >> 6;
    const int n0 = cg << 2;
    const int row0 = cid * 32;
    int rb[8];
    #pragma unroll
    for (int r = 0; r < 8; r++) rb[r] = (rg*8 + r) * kpad;

    for (int t = 0; t < S_; t++){
        // ---- load x_t into inbuf[:, 0:kin) ----
        if ((kin & 3) == 0){
            const float4* src = (const float4*)(in_seq + ((size_t)t*B_ + row0)*kin);
            int n4 = (32*kin) >> 2;
            for (int idx = tid; idx < n4; idx += 256){
                int e = idx << 2; int m = e / kin; int k = e - m*kin;
                *(float4*)&inbuf[m*kpad + k] = src[idx];
            }
        } else {
            const float* src = in_seq + ((size_t)t*B_ + row0)*kin;
            for (int idx = tid; idx < 32*kin; idx += 256){
                int m = idx / kin, k = idx - m*kin;
                inbuf[m*kpad + k] = src[idx];
            }
        }
        __syncthreads();

        // ---- gates: thread tile 8 rows x 4 cols, f32x2 paired over K ----
        unsigned long long acc[8][4];
        float4 b4 = *(const float4*)&bias_s[n0];
        #pragma unroll
        for (int r = 0; r < 8; r++){
            acc[r][0] = pack2(b4.x, 0.f); acc[r][1] = pack2(b4.y, 0.f);
            acc[r][2] = pack2(b4.z, 0.f); acc[r][3] = pack2(b4.w, 0.f);
        }
        for (int k = 0; k < kpad; k += 4){
            const float* wp0 = Wp + (k >> 1)*512 + (n0 << 1);
            ulonglong2 wa = *(const ulonglong2*)(wp0);        // (k,k+1) pairs, cols n0,n0+1
            ulonglong2 wb = *(const ulonglong2*)(wp0 + 4);    // cols n0+2,n0+3
            ulonglong2 wc = *(const ulonglong2*)(wp0 + 512);  // (k+2,k+3) pairs, n0,n0+1
            ulonglong2 wd = *(const ulonglong2*)(wp0 + 516);
            #pragma unroll
            for (int r = 0; r < 8; r++){
                ulonglong2 xu = *(const ulonglong2*)&inbuf[rb[r] + k];
                fma2(acc[r][0], xu.x, wa.x);
                fma2(acc[r][1], xu.x, wa.y);
                fma2(acc[r][2], xu.x, wb.x);
                fma2(acc[r][3], xu.x, wb.y);
                fma2(acc[r][0], xu.y, wc.x);
                fma2(acc[r][1], xu.y, wc.y);
                fma2(acc[r][2], xu.y, wd.x);
                fma2(acc[r][3], xu.y, wd.y);
            }
        }
        #pragma unroll
        for (int r = 0; r < 8; r++){
            float2 a0 = unpack2(acc[r][0]), a1 = unpack2(acc[r][1]);
            float2 a2 = unpack2(acc[r][2]), a3 = unpack2(acc[r][3]);
            *(float4*)&gates[(rg*8 + r)*256 + n0] =
                make_float4(a0.x + a0.y, a1.x + a1.y, a2.x + a2.y, a3.x + a3.y);
        }
        __syncthreads();

        // ---- cell update ----
        for (int idx = tid; idx < 32*H_; idx += 256){
            int m = idx >> 6, j = idx & 63;
            const float* gm = gates + m*256;
            float gi = gm[j], gf = gm[64 + j], gg = gm[128 + j], go = gm[192 + j];
            float c = sig_(gf)*c_s[idx] + sig_(gi)*tanh_(gg);
            c_s[idx] = c;
            float h = sig_(go)*tanh_(c);
            inbuf[m*kpad + kin + j] = h;
            if (ys) ys[((size_t)t*B_ + row0 + m)*H_ + j] = h;
            if (hf && t == S_-1) hf[(row0 + m)*H_ + j] = h;
        }
        __syncthreads();
    }
}

// ---------------- VQ epilogue ----------------
__global__ void zero_k(){
    int t = threadIdx.x;
    if (t < NEMB) g_counts[t] = 0;
    if (t == 0)   g_sqsum = 0.f;
}

__global__ void vq_final(const float* __restrict__ proj_w, const float* __restrict__ proj_b,
                         const float* __restrict__ codebook, float* __restrict__ out)
{
    __shared__ float pw[EDIM*H_];
    __shared__ float pb[EDIM];
    __shared__ float cb[NEMB*EDIM];
    __shared__ float cn2[NEMB];
    __shared__ float red[256];
    int tid = threadIdx.x;
    for (int i = tid; i < EDIM*H_;   i += 256) pw[i] = proj_w[i];
    for (int i = tid; i < NEMB*EDIM; i += 256) cb[i] = codebook[i];
    if (tid < EDIM) pb[tid] = proj_b[tid];
    __syncthreads();
    if (tid < NEMB){
        float s = 0.f;
        #pragma unroll
        for (int e = 0; e < EDIM; e++){ float v = cb[tid*EDIM + e]; s = fmaf(v, v, s); }
        cn2[tid] = s;
    }
    __syncthreads();

    int b = blockIdx.x*256 + tid;
    float h[H_];
    const float4* hp = (const float4*)&g_vq_hid[b*H_];
    #pragma unroll
    for (int i = 0; i < H_/4; i++){
        float4 v = hp[i]; h[4*i] = v.x; h[4*i+1] = v.y; h[4*i+2] = v.z; h[4*i+3] = v.w;
    }
    float p[EDIM]; float p2 = 0.f;
    #pragma unroll
    for (int e = 0; e < EDIM; e++){
        float a = pb[e];
        #pragma unroll
        for (int d = 0; d < H_; d++) a = fmaf(pw[e*H_ + d], h[d], a);
        p[e] = a; p2 = fmaf(a, a, p2);
    }
    int best = 0; float dmin = 3.4e38f;
    #pragma unroll 4
    for (int n = 0; n < NEMB; n++){
        float dot = 0.f;
        #pragma unroll
        for (int e = 0; e < EDIM; e++) dot = fmaf(cb[n*EDIM + e], p[e], dot);
        float d = p2 + cn2[n] - 2.f*dot;
        if (d < dmin){ dmin = d; best = n; }
    }
    // residual sum of squares (exact form for e_loss/q_loss)
    float rs = 0.f;
    #pragma unroll
    for (int e = 0; e < EDIM; e++){ float r = cb[best*EDIM + e] - p[e]; rs = fmaf(r, r, rs); }
    red[tid] = rs;
    atomicAdd(&g_counts[best], 1);

    // write combined = [cnn_feat(64) | quantized(32)] twice
    const float* cf = &g_cnn_feat[b*H_];
    float* o0 = out + (size_t)b*96;
    float* o1 = out + (size_t)B_*96 + (size_t)b*96;
    #pragma unroll
    for (int j = 0; j < H_; j++){ float v = cf[j]; o0[j] = v; o1[j] = v; }
    #pragma unroll
    for (int e = 0; e < EDIM; e++){ float v = cb[best*EDIM + e]; o0[H_+e] = v; o1[H_+e] = v; }

    __syncthreads();
    for (int st = 128; st > 0; st >>= 1){
        if (tid < st) red[tid] += red[tid + st];
        __syncthreads();
    }
    if (tid == 0) atomicAdd(&g_sqsum, red[0]);
}

__global__ void finalize_k(float* __restrict__ out){
    if (threadIdx.x == 0){
        float msq = g_sqsum / (float)(B_*EDIM);
        out[(size_t)2*B_*96]     = msq + 0.01f * msq;        // q_loss + COMMIT*e_loss
        float ent = 0.f;
        for (int n = 0; n < NEMB; n++){
            float ap = (float)g_counts[n] / (float)B_;
            ent += ap * logf(ap + 1e-10f);
        }
        out[(size_t)2*B_*96 + 1] = expf(-ent);
    }
}

// ---------------- launch ----------------
extern "C" void kernel_launch(void* const* d_in, const int* in_sizes, int n_in,
                              void* d_out, int out_size)
{
    const float* x       = (const float*)d_in[0];
    const float* conv_w  = (const float*)d_in[1];
    const float* conv_b  = (const float*)d_in[2];
    const float* bn_g    = (const float*)d_in[3];
    const float* bn_b    = (const float*)d_in[4];
    const float* bn_m    = (const float*)d_in[5];
    const float* bn_v    = (const float*)d_in[6];
    const float* c0_wih  = (const float*)d_in[7];
    const float* c0_whh  = (const float*)d_in[8];
    const float* c0_bih  = (const float*)d_in[9];
    const float* c0_bhh  = (const float*)d_in[10];
    const float* c1_wih  = (const float*)d_in[11];
    const float* c1_whh  = (const float*)d_in[12];
    const float* c1_bih  = (const float*)d_in[13];
    const float* c1_bhh  = (const float*)d_in[14];
    const float* v0_wih  = (const float*)d_in[15];
    const float* v0_whh  = (const float*)d_in[16];
    const float* v0_bih  = (const float*)d_in[17];
    const float* v0_bhh  = (const float*)d_in[18];
    const float* v1_wih  = (const float*)d_in[19];
    const float* v1_whh  = (const float*)d_in[20];
    const float* v1_bih  = (const float*)d_in[21];
    const float* v1_bhh  = (const float*)d_in[22];
    const float* proj_w  = (const float*)d_in[23];
    const float* proj_b  = (const float*)d_in[24];
    const float* codebook= (const float*)d_in[25];
    float* out = (float*)d_out;

    // smem: layer0 max (kpad=96): (96*256+256+32*96+32*256+32*64)*4 = 152576 B
    //       layer1 (kpad=128):   (128*256+256+32*128+32*256+32*64)*4 = 189440 B
    cudaFuncSetAttribute(lstm_pair, cudaFuncAttributeMaxDynamicSharedMemorySize, 189440);

    prep_kernel<<<(B_*S_)/256, 256>>>(x, conv_w, conv_b, bn_g, bn_b, bn_m, bn_v);
    zero_k<<<1, 64>>>();
    lstm_pair<<<128, 256, 152576>>>(0, c0_wih, c0_whh, c0_bih, c0_bhh,
                                       v0_wih, v0_whh, v0_bih, v0_bhh);
    lstm_pair<<<128, 256, 189440>>>(1, c1_wih, c1_whh, c1_bih, c1_bhh,
                                       v1_wih, v1_whh, v1_bih, v1_bhh);
    vq_final<<<B_/256, 256>>>(proj_w, proj_b, codebook, out);
    finalize_k<<<1, 64>>>(out);
}

// round 4
// speedup vs baseline: 1.1491x; 1.1491x over previous
#include <cuda_runtime.h>
#include <cstdint>

#define B_   2048
#define S_   512
#define DIN  5
#define H_   64
#define CC   32
#define EDIM 32
#define NEMB 64

// ---------------- static device scratch (allocation-free rule) ----------------
__device__ __align__(16) float g_convout[(size_t)S_*B_*CC];   // [S][B][32]
__device__ __align__(16) float g_xT[(size_t)S_*B_*8];         // [S][B][5] (stride 5, padded alloc)
__device__ __align__(16) float g_ys_cnn[(size_t)S_*B_*H_];    // [S][B][64]
__device__ __align__(16) float g_ys_vq[(size_t)S_*B_*H_];     // [S][B][64]
__device__ __align__(16) float g_cnn_feat[B_*H_];
__device__ __align__(16) float g_vq_hid[B_*H_];
__device__ float g_sqsum;
__device__ int   g_counts[NEMB];

// ---------------- helpers ----------------
__device__ __forceinline__ void fma2(unsigned long long& d, unsigned long long a, unsigned long long b){
    asm("fma.rn.f32x2 %0, %1, %2, %0;" : "+l"(d) : "l"(a), "l"(b));
}
__device__ __forceinline__ float2 unpack2(unsigned long long v){
    float2 r; asm("mov.b64 {%0,%1}, %2;" : "=f"(r.x), "=f"(r.y) : "l"(v)); return r;
}
__device__ __forceinline__ float sig_(float x){ return __fdividef(1.f, 1.f + __expf(-x)); }
__device__ __forceinline__ float tanh_(float x){ return __fdividef(2.f, 1.f + __expf(-2.f*x)) - 1.f; }

// ---------------- prep: conv1d(k=3,pad=1) + BN(eval) + ReLU, and x transpose ----------------
__global__ void prep_kernel(const float* __restrict__ x, const float* __restrict__ conv_w,
                            const float* __restrict__ conv_b, const float* __restrict__ bn_g,
                            const float* __restrict__ bn_b, const float* __restrict__ bn_m,
                            const float* __restrict__ bn_v)
{
    __shared__ float ws[CC*15];
    __shared__ float bs[CC];
    int tid = threadIdx.x;
    for (int idx = tid; idx < CC*15; idx += 256){
        int c = idx / 15;
        float sc = bn_g[c] * rsqrtf(bn_v[c] + 1e-5f);
        ws[idx] = conv_w[idx] * sc;
    }
    if (tid < CC){
        float sc = bn_g[tid] * rsqrtf(bn_v[tid] + 1e-5f);
        bs[tid] = (conv_b[tid] - bn_m[tid]) * sc + bn_b[tid];
    }
    __syncthreads();

    int gid = blockIdx.x * 256 + tid;        // gid = b*S + s
    int s = gid & (S_-1);
    size_t xb = (size_t)gid * DIN;
    int b = gid >> 9;
    float x0[DIN], xm[DIN], xp[DIN];
    #pragma unroll
    for (int i = 0; i < DIN; i++){
        x0[i] = x[xb + i];
        xm[i] = (s > 0)      ? x[xb - DIN + i] : 0.f;
        xp[i] = (s < S_-1)   ? x[xb + DIN + i] : 0.f;
    }
    float o[CC];
    #pragma unroll
    for (int c = 0; c < CC; c++){
        float acc = bs[c];
        #pragma unroll
        for (int i = 0; i < DIN; i++){
            acc = fmaf(xm[i], ws[c*15 + i*3 + 0], acc);
            acc = fmaf(x0[i], ws[c*15 + i*3 + 1], acc);
            acc = fmaf(xp[i], ws[c*15 + i*3 + 2], acc);
        }
        o[c] = fmaxf(acc, 0.f);
    }
    float4* dst = (float4*)&g_convout[((size_t)s*B_ + b)*CC];
    #pragma unroll
    for (int c = 0; c < CC/4; c++) dst[c] = make_float4(o[4*c], o[4*c+1], o[4*c+2], o[4*c+3]);
    float* xt = &g_xT[((size_t)s*B_ + b)*DIN];
    #pragma unroll
    for (int i = 0; i < DIN; i++) xt[i] = x0[i];
}

// ---------------- fused 2-stream LSTM layer kernel (K-split, 512 thr) ----------------
// 128 CTAs: [0,64)=stream A(cnn), [64,128)=stream B(vq). 32 batch rows/CTA.
// half=tid>>8 k-split. Thread tile: 8 rows x 4 gates at column j=tid&63 over
// k-range [half*kh, (half+1)*kh). inbuf row layout: x at [0,kin), zeros [kin,hoff),
// h at [hoff, hoff+64) with hoff=(kin+3)&~3 so all float4 accesses stay aligned.
__global__ void __launch_bounds__(512, 1) lstm_pair(int layer,
    const float* __restrict__ wihA, const float* __restrict__ whhA,
    const float* __restrict__ bihA, const float* __restrict__ bhhA,
    const float* __restrict__ wihB, const float* __restrict__ whhB,
    const float* __restrict__ bihB, const float* __restrict__ bhhB)
{
    extern __shared__ float sm[];
    int tid = threadIdx.x;
    bool strA = blockIdx.x < 64;
    int cid = strA ? blockIdx.x : blockIdx.x - 64;

    const float *wih, *whh, *bih, *bhh, *in_seq;
    float *ys = nullptr, *hf = nullptr;
    int kin, kpad;
    if (layer == 0){
        if (strA){ in_seq = g_convout; kin = CC;  kpad = 96; wih=wihA; whh=whhA; bih=bihA; bhh=bhhA; ys = g_ys_cnn; }
        else     { in_seq = g_xT;      kin = DIN; kpad = 72; wih=wihB; whh=whhB; bih=bihB; bhh=bhhB; ys = g_ys_vq; }
    } else {
        if (strA){ in_seq = g_ys_cnn;  kin = H_;  kpad = 128; wih=wihA; whh=whhA; bih=bihA; bhh=bhhA; hf = g_cnn_feat; }
        else     { in_seq = g_ys_vq;   kin = H_;  kpad = 128; wih=wihB; whh=whhB; bih=bihB; bhh=bhhB; hf = g_vq_hid; }
    }
    const int kh   = kpad >> 1;
    const int hoff = (kin + 3) & ~3;      // aligned start of h within inbuf row

    float* Wp     = sm;                    // kpad*256 (two regions of kh*256)
    float* bias_s = Wp + kpad*256;         // 256
    float* inbuf  = bias_s + 256;          // 32*kpad : [x_t | pad | h | pad]
    float* gpart  = inbuf + 32*kpad;       // 32*256 : B-half partial gates [row][j][4]
    float* c_s    = gpart + 32*256;        // 32*64

    // one-time staging: weight slot k -> wih for k<kin, whh for k in [hoff,hoff+64)
    for (int idx = tid; idx < 256*kpad; idx += 512){
        int n = idx / kpad, k = idx - n*kpad;
        int g = n >> 6, j = n & 63;
        float v = 0.f;
        if (k < kin)                          v = wih[n*kin + k];
        else if (k >= hoff && k < hoff + H_)  v = whh[n*H_ + (k - hoff)];
        Wp[(g>>1)*(kh*256) + (k>>1)*256 + j*4 + (g&1)*2 + (k&1)] = v;
    }
    if (tid < 256) bias_s[tid] = bih[tid] + bhh[tid];
    for (int idx = tid; idx < 32*kpad; idx += 512) inbuf[idx] = 0.f;
    for (int idx = tid; idx < 32*H_;   idx += 512) c_s[idx]   = 0.f;
    __syncthreads();

    const int j    = tid & 63;
    const int rg   = (tid >> 6) & 3;
    const int half = tid >> 8;            // 0 = update half, 1 = prefetch half
    const int btid = tid & 255;
    const int row0 = cid * 32;
    const int kbeg = half * kh;
    const int j4   = j << 2;
    const float* WAh = Wp;
    const float* WBh = Wp + kh*256;
    int rb[8];
    #pragma unroll
    for (int r = 0; r < 8; r++) rb[r] = (rg*8 + r) * kpad;

    float bi=0.f, bf=0.f, bg=0.f, bo=0.f;
    if (half == 0){ bi = bias_s[j]; bf = bias_s[64+j]; bg = bias_s[128+j]; bo = bias_s[192+j]; }

    // preload x_0 (B half)
    if (half == 1){
        if ((kin & 3) == 0){
            const float4* src = (const float4*)(in_seq + ((size_t)0*B_ + row0)*kin);
            int n4 = (32*kin) >> 2;
            for (int i = btid; i < n4; i += 256){
                int e = i << 2; int m = e / kin; int kk = e - m*kin;
                *(float4*)&inbuf[m*kpad + kk] = src[i];
            }
        } else {
            const float* src = in_seq + ((size_t)0*B_ + row0)*kin;
            for (int i = btid; i < 32*kin; i += 256){
                int m = i / kin, kk = i - m*kin;
                inbuf[m*kpad + kk] = src[i];
            }
        }
    }
    __syncthreads();

    for (int t = 0; t < S_; t++){
        // B: stream out ys(t-1) while gates start (h_{t-1} intact until post-sync update)
        if (half == 1 && ys && t > 0){
            for (int i = btid; i < 512; i += 256){
                int m = i >> 4, q = (i & 15) << 2;
                float4 v = *(float4*)&inbuf[m*kpad + hoff + q];
                *(float4*)&ys[((size_t)(t-1)*B_ + row0 + m)*H_ + q] = v;
            }
        }

        // ---- gate partials: 8 rows x 4 gates, f32x2 over this half's K range ----
        unsigned long long acc[8][4];
        #pragma unroll
        for (int r = 0; r < 8; r++){
            acc[r][0] = 0ull; acc[r][1] = 0ull; acc[r][2] = 0ull; acc[r][3] = 0ull;
        }
        for (int k = kbeg; k < kbeg + kh; k += 4){
            int kp = k >> 1;
            const float* a0p = WAh + kp*256 + j4;
            const float* b0p = WBh + kp*256 + j4;
            ulonglong2 wA0 = *(const ulonglong2*)a0p;
            ulonglong2 wB0 = *(const ulonglong2*)b0p;
            ulonglong2 wA1 = *(const ulonglong2*)(a0p + 256);
            ulonglong2 wB1 = *(const ulonglong2*)(b0p + 256);
            #pragma unroll
            for (int r = 0; r < 8; r++){
                ulonglong2 xu = *(const ulonglong2*)&inbuf[rb[r] + k];
                fma2(acc[r][0], xu.x, wA0.x);
                fma2(acc[r][1], xu.x, wA0.y);
                fma2(acc[r][2], xu.x, wB0.x);
                fma2(acc[r][3], xu.x, wB0.y);
                fma2(acc[r][0], xu.y, wA1.x);
                fma2(acc[r][1], xu.y, wA1.y);
                fma2(acc[r][2], xu.y, wB1.x);
                fma2(acc[r][3], xu.y, wB1.y);
            }
        }
        if (half == 1){
            #pragma unroll
            for (int r = 0; r < 8; r++){
                int row = rg*8 + r;
                float2 a0 = unpack2(acc[r][0]), a1 = unpack2(acc[r][1]);
                float2 a2 = unpack2(acc[r][2]), a3 = unpack2(acc[r][3]);
                *(float4*)&gpart[row*256 + j4] =
                    make_float4(a0.x + a0.y, a1.x + a1.y, a2.x + a2.y, a3.x + a3.y);
            }
        }
        __syncthreads();

        if (half == 0){
            // ---- combine + cell update ----
            #pragma unroll
            for (int r = 0; r < 8; r++){
                int row = rg*8 + r;
                float4 gp = *(const float4*)&gpart[row*256 + j4];
                float2 a0 = unpack2(acc[r][0]), a1 = unpack2(acc[r][1]);
                float2 a2 = unpack2(acc[r][2]), a3 = unpack2(acc[r][3]);
                float gi = a0.x + a0.y + gp.x + bi;
                float gf = a1.x + a1.y + gp.y + bf;
                float gg = a2.x + a2.y + gp.z + bg;
                float go = a3.x + a3.y + gp.w + bo;
                float c = sig_(gf)*c_s[row*H_ + j] + sig_(gi)*tanh_(gg);
                c_s[row*H_ + j] = c;
                float h = sig_(go)*tanh_(c);
                inbuf[rb[r] + hoff + j] = h;
                if (hf && t == S_-1) hf[(row0 + row)*H_ + j] = h;
            }
        } else {
            // ---- prefetch x_{t+1} ----
            if (t + 1 < S_){
                if ((kin & 3) == 0){
                    const float4* src = (const float4*)(in_seq + ((size_t)(t+1)*B_ + row0)*kin);
                    int n4 = (32*kin) >> 2;
                    for (int i = btid; i < n4; i += 256){
                        int e = i << 2; int m = e / kin; int kk = e - m*kin;
                        *(float4*)&inbuf[m*kpad + kk] = src[i];
                    }
                } else {
                    const float* src = in_seq + ((size_t)(t+1)*B_ + row0)*kin;
                    for (int i = btid; i < 32*kin; i += 256){
                        int m = i / kin, kk = i - m*kin;
                        inbuf[m*kpad + kk] = src[i];
                    }
                }
            }
        }
        __syncthreads();
    }
    if (half == 1 && ys){
        for (int i = btid; i < 512; i += 256){
            int m = i >> 4, q = (i & 15) << 2;
            float4 v = *(float4*)&inbuf[m*kpad + hoff + q];
            *(float4*)&ys[((size_t)(S_-1)*B_ + row0 + m)*H_ + q] = v;
        }
    }
}

// ---------------- VQ epilogue ----------------
__global__ void zero_k(){
    int t = threadIdx.x;
    if (t < NEMB) g_counts[t] = 0;
    if (t == 0)   g_sqsum = 0.f;
}

__global__ void vq_final(const float* __restrict__ proj_w, const float* __restrict__ proj_b,
                         const float* __restrict__ codebook, float* __restrict__ out)
{
    __shared__ float pw[EDIM*H_];
    __shared__ float pb[EDIM];
    __shared__ float cb[NEMB*EDIM];
    __shared__ float cn2[NEMB];
    __shared__ float red[256];
    int tid = threadIdx.x;
    for (int i = tid; i < EDIM*H_;   i += 256) pw[i] = proj_w[i];
    for (int i = tid; i < NEMB*EDIM; i += 256) cb[i] = codebook[i];
    if (tid < EDIM) pb[tid] = proj_b[tid];
    __syncthreads();
    if (tid < NEMB){
        float s = 0.f;
        #pragma unroll
        for (int e = 0; e < EDIM; e++){ float v = cb[tid*EDIM + e]; s = fmaf(v, v, s); }
        cn2[tid] = s;
    }
    __syncthreads();

    int b = blockIdx.x*256 + tid;
    float h[H_];
    const float4* hp = (const float4*)&g_vq_hid[b*H_];
    #pragma unroll
    for (int i = 0; i < H_/4; i++){
        float4 v = hp[i]; h[4*i] = v.x; h[4*i+1] = v.y; h[4*i+2] = v.z; h[4*i+3] = v.w;
    }
    float p[EDIM]; float p2 = 0.f;
    #pragma unroll
    for (int e = 0; e < EDIM; e++){
        float a = pb[e];
        #pragma unroll
        for (int d = 0; d < H_; d++) a = fmaf(pw[e*H_ + d], h[d], a);
        p[e] = a; p2 = fmaf(a, a, p2);
    }
    int best = 0; float dmin = 3.4e38f;
    #pragma unroll 4
    for (int n = 0; n < NEMB; n++){
        float dot = 0.f;
        #pragma unroll
        for (int e = 0; e < EDIM; e++) dot = fmaf(cb[n*EDIM + e], p[e], dot);
        float d = p2 + cn2[n] - 2.f*dot;
        if (d < dmin){ dmin = d; best = n; }
    }
    float rs = 0.f;
    #pragma unroll
    for (int e = 0; e < EDIM; e++){ float r = cb[best*EDIM + e] - p[e]; rs = fmaf(r, r, rs); }
    red[tid] = rs;
    atomicAdd(&g_counts[best], 1);

    const float* cf = &g_cnn_feat[b*H_];
    float* o0 = out + (size_t)b*96;
    float* o1 = out + (size_t)B_*96 + (size_t)b*96;
    #pragma unroll
    for (int jj = 0; jj < H_; jj++){ float v = cf[jj]; o0[jj] = v; o1[jj] = v; }
    #pragma unroll
    for (int e = 0; e < EDIM; e++){ float v = cb[best*EDIM + e]; o0[H_+e] = v; o1[H_+e] = v; }

    __syncthreads();
    for (int st = 128; st > 0; st >>= 1){
        if (tid < st) red[tid] += red[tid + st];
        __syncthreads();
    }
    if (tid == 0) atomicAdd(&g_sqsum, red[0]);
}

__global__ void finalize_k(float* __restrict__ out){
    if (threadIdx.x == 0){
        float msq = g_sqsum / (float)(B_*EDIM);
        out[(size_t)2*B_*96]     = msq + 0.01f * msq;
        float ent = 0.f;
        for (int n = 0; n < NEMB; n++){
            float ap = (float)g_counts[n] / (float)B_;
            ent += ap * logf(ap + 1e-10f);
        }
        out[(size_t)2*B_*96 + 1] = expf(-ent);
    }
}

// ---------------- launch ----------------
extern "C" void kernel_launch(void* const* d_in, const int* in_sizes, int n_in,
                              void* d_out, int out_size)
{
    const float* x       = (const float*)d_in[0];
    const float* conv_w  = (const float*)d_in[1];
    const float* conv_b  = (const float*)d_in[2];
    const float* bn_g    = (const float*)d_in[3];
    const float* bn_b    = (const float*)d_in[4];
    const float* bn_m    = (const float*)d_in[5];
    const float* bn_v    = (const float*)d_in[6];
    const float* c0_wih  = (const float*)d_in[7];
    const float* c0_whh  = (const float*)d_in[8];
    const float* c0_bih  = (const float*)d_in[9];
    const float* c0_bhh  = (const float*)d_in[10];
    const float* c1_wih  = (const float*)d_in[11];
    const float* c1_whh  = (const float*)d_in[12];
    const float* c1_bih  = (const float*)d_in[13];
    const float* c1_bhh  = (const float*)d_in[14];
    const float* v0_wih  = (const float*)d_in[15];
    const float* v0_whh  = (const float*)d_in[16];
    const float* v0_bih  = (const float*)d_in[17];
    const float* v0_bhh  = (const float*)d_in[18];
    const float* v1_wih  = (const float*)d_in[19];
    const float* v1_whh  = (const float*)d_in[20];
    const float* v1_bih  = (const float*)d_in[21];
    const float* v1_bhh  = (const float*)d_in[22];
    const float* proj_w  = (const float*)d_in[23];
    const float* proj_b  = (const float*)d_in[24];
    const float* codebook= (const float*)d_in[25];
    float* out = (float*)d_out;

    // smem bytes: (kpad*256 + 256 + 32*kpad + 32*256 + 32*64)*4
    // layer0 (kpad=96): 152576 ; layer1 (kpad=128): 189440
    cudaFuncSetAttribute(lstm_pair, cudaFuncAttributeMaxDynamicSharedMemorySize, 189440);

    prep_kernel<<<(B_*S_)/256, 256>>>(x, conv_w, conv_b, bn_g, bn_b, bn_m, bn_v);
    zero_k<<<1, 64>>>();
    lstm_pair<<<128, 512, 152576>>>(0, c0_wih, c0_whh, c0_bih, c0_bhh,
                                       v0_wih, v0_whh, v0_bih, v0_bhh);
    lstm_pair<<<128, 512, 189440>>>(1, c1_wih, c1_whh, c1_bih, c1_bhh,
                                       v1_wih, v1_whh, v1_bih, v1_bhh);
    vq_final<<<B_/256, 256>>>(proj_w, proj_b, codebook, out);
    finalize_k<<<1, 64>>>(out);
}

// round 8
// speedup vs baseline: 2.0375x; 1.7731x over previous
#include <cuda_runtime.h>
#include <cuda_fp16.h>
#include <cstdint>

#define B_   2048
#define S_   512
#define DIN  5
#define H_   64
#define CC   32
#define EDIM 32
#define NEMB 64

// ---------------- static device scratch ----------------
__device__ __align__(16) float g_convout[(size_t)S_*B_*CC];   // [S][B][32]
__device__ __align__(16) float g_xT[(size_t)S_*B_*8];         // [S][B][5] stride 5
__device__ __align__(16) float g_ys_cnn[(size_t)S_*B_*H_];
__device__ __align__(16) float g_ys_vq[(size_t)S_*B_*H_];
__device__ __align__(16) float g_cnn_feat[B_*H_];
__device__ __align__(16) float g_vq_hid[B_*H_];
__device__ float g_sqsum;
__device__ int   g_counts[NEMB];

// ---------------- helpers ----------------
__device__ __forceinline__ float sig_(float x){ return __fdividef(1.f, 1.f + __expf(-x)); }
__device__ __forceinline__ float tanh_(float x){ return __fdividef(2.f, 1.f + __expf(-2.f*x)) - 1.f; }

__device__ __forceinline__ uint32_t smem_u32(const void* p){
    uint32_t a; asm("{ .reg .u64 t; cvta.to.shared.u64 t, %1; cvt.u32.u64 %0, t; }" : "=r"(a) : "l"(p)); return a;
}
__device__ __forceinline__ void ldsm4(uint32_t* r, uint32_t addr){
    asm volatile("ldmatrix.sync.aligned.m8n8.x4.shared.b16 {%0,%1,%2,%3}, [%4];"
        : "=r"(r[0]), "=r"(r[1]), "=r"(r[2]), "=r"(r[3]) : "r"(addr));
}
__device__ __forceinline__ void mma16816(float* c, const uint32_t* a, uint32_t b0, uint32_t b1){
    asm volatile("mma.sync.aligned.m16n8k16.row.col.f32.f16.f16.f32 "
        "{%0,%1,%2,%3}, {%4,%5,%6,%7}, {%8,%9}, {%0,%1,%2,%3};"
        : "+f"(c[0]), "+f"(c[1]), "+f"(c[2]), "+f"(c[3])
        : "r"(a[0]), "r"(a[1]), "r"(a[2]), "r"(a[3]), "r"(b0), "r"(b1));
}

// smem byte offsets (single layout for all layers; A staging sized for K=128)
#define STRD   136              // halves per X/A row (pad for bank-conflict-free ldmatrix)
#define GSTRD  260              // floats per gates row (conflict-free scatter)
#define OFF_BHI   0                                  // [32][136] fp16 = 8704
#define OFF_BLO   8704                               // 8704
#define OFF_G     17408                              // [32][260] f32 = 33280
#define OFF_BIAS  50688                              // 1024
#define OFF_AHI   51712                              // [256][136] fp16 = 69632
#define OFF_ALO   121344                             // 69632
#define SMEM_TOT  190976

// ---------------- prep: conv1d + BN + ReLU + transpose ----------------
__global__ void prep_kernel(const float* __restrict__ x, const float* __restrict__ conv_w,
                            const float* __restrict__ conv_b, const float* __restrict__ bn_g,
                            const float* __restrict__ bn_b, const float* __restrict__ bn_m,
                            const float* __restrict__ bn_v)
{
    __shared__ float ws[CC*15];
    __shared__ float bs[CC];
    int tid = threadIdx.x;
    for (int idx = tid; idx < CC*15; idx += 256){
        int c = idx / 15;
        float sc = bn_g[c] * rsqrtf(bn_v[c] + 1e-5f);
        ws[idx] = conv_w[idx] * sc;
    }
    if (tid < CC){
        float sc = bn_g[tid] * rsqrtf(bn_v[tid] + 1e-5f);
        bs[tid] = (conv_b[tid] - bn_m[tid]) * sc + bn_b[tid];
    }
    __syncthreads();

    int gid = blockIdx.x * 256 + tid;   // gid = b*S + s
    int s = gid & (S_-1);
    size_t xb = (size_t)gid * DIN;
    int b = gid >> 9;
    float x0[DIN], xm[DIN], xp[DIN];
    #pragma unroll
    for (int i = 0; i < DIN; i++){
        x0[i] = x[xb + i];
        xm[i] = (s > 0)    ? x[xb - DIN + i] : 0.f;
        xp[i] = (s < S_-1) ? x[xb + DIN + i] : 0.f;
    }
    float o[CC];
    #pragma unroll
    for (int c = 0; c < CC; c++){
        float acc = bs[c];
        #pragma unroll
        for (int i = 0; i < DIN; i++){
            acc = fmaf(xm[i], ws[c*15 + i*3 + 0], acc);
            acc = fmaf(x0[i], ws[c*15 + i*3 + 1], acc);
            acc = fmaf(xp[i], ws[c*15 + i*3 + 2], acc);
        }
        o[c] = fmaxf(acc, 0.f);
    }
    float4* dst = (float4*)&g_convout[((size_t)s*B_ + b)*CC];
    #pragma unroll
    for (int c = 0; c < CC/4; c++) dst[c] = make_float4(o[4*c], o[4*c+1], o[4*c+2], o[4*c+3]);
    float* xt = &g_xT[((size_t)s*B_ + b)*DIN];
    #pragma unroll
    for (int i = 0; i < DIN; i++) xt[i] = x0[i];
}

// ---------------- HMMA split-fp16 LSTM stream ----------------
// 512 threads, 16 warps. warp w: gate rows [16w,16w+16), full N=32, K = KT*16.
// X tile row layout: x at [0,KIN), zeros [KIN,HOFF), h at [HOFF,HOFF+64), HOFF+64 == KT*16.
template<int KT, int KIN, int HOFF>
__device__ void lstm_stream(char* smem, const float* __restrict__ in_seq,
                            float* __restrict__ ys, float* __restrict__ hf, int row0,
                            const float* __restrict__ wih, const float* __restrict__ whh,
                            const float* __restrict__ bih, const float* __restrict__ bhh)
{
    const int tid  = threadIdx.x;
    const int lane = tid & 31;
    const int w    = tid >> 5;
    constexpr int K = KT * 16;

    __half* Bhi   = (__half*)(smem + OFF_BHI);
    __half* Blo   = (__half*)(smem + OFF_BLO);
    float*  gates = (float*)(smem + OFF_G);
    float*  bias_s= (float*)(smem + OFF_BIAS);
    __half* Ahi   = (__half*)(smem + OFF_AHI);
    __half* Alo   = (__half*)(smem + OFF_ALO);

    // ---- stage split weights ----
    for (int idx = tid; idx < 256*K; idx += 512){
        int n = idx / K, k = idx - n*K;
        float v = 0.f;
        if (k < KIN)                          v = wih[n*KIN + k];
        else if (k >= HOFF && k < HOFF + H_)  v = whh[n*H_ + (k - HOFF)];
        __half hi = __float2half_rn(v);
        __half lo = __float2half_rn(v - __half2float(hi));
        Ahi[n*STRD + k] = hi;
        Alo[n*STRD + k] = lo;
    }
    if (tid < 256) bias_s[tid] = bih[tid] + bhh[tid];
    for (int idx = tid; idx < 32*STRD; idx += 512){
        Bhi[idx] = __float2half_rn(0.f);
        Blo[idx] = __float2half_rn(0.f);
    }
    __syncthreads();

    // ---- load A fragments to registers (resident across all timesteps) ----
    uint32_t ahi[KT][4], alo[KT][4];
    {
        int arow = (w << 4) + (lane & 7) + (((lane >> 3) & 1) << 3);
        uint32_t bh = smem_u32(Ahi) + (uint32_t)(arow * STRD) * 2u;
        uint32_t bl = smem_u32(Alo) + (uint32_t)(arow * STRD) * 2u;
        #pragma unroll
        for (int kt = 0; kt < KT; kt++){
            uint32_t off = (uint32_t)(kt*16 + ((lane >> 4) << 3)) * 2u;
            ldsm4(ahi[kt], bh + off);
            ldsm4(alo[kt], bl + off);
        }
    }

    // x loader/converter
    auto load_x = [&](int t){
        for (int idx = tid; idx < 32*KIN; idx += 512){
            int r = idx / KIN, k = idx - r*KIN;
            float v = in_seq[((size_t)t*B_ + row0 + r)*KIN + k];
            __half hi = __float2half_rn(v);
            Bhi[r*STRD + k] = hi;
            Blo[r*STRD + k] = __float2half_rn(v - __half2float(hi));
        }
    };
    load_x(0);
    __syncthreads();

    // B ldmatrix lane addressing (two x4 per split per k-tile: n0-15, n16-31)
    const int bn = ((lane >> 4) << 3) + (lane & 7);
    const int bk = ((lane >> 3) & 1) << 3;
    const uint32_t bh0 = smem_u32(Bhi) + (uint32_t)(bn*STRD + bk) * 2u;
    const uint32_t bh1 = bh0 + 16u*STRD*2u;
    const uint32_t bl0 = smem_u32(Blo) + (uint32_t)(bn*STRD + bk) * 2u;
    const uint32_t bl1 = bl0 + 16u*STRD*2u;

    const int gq  = lane >> 2, tig = lane & 3;
    const int G0  = (w << 4) + gq;
    const int urow = tid >> 4;
    const int j0   = (tid & 15) << 2;
    float cst[4] = {0.f, 0.f, 0.f, 0.f};

    for (int t = 0; t < S_; t++){
        // ---- GEMM: 12 HMMA per k-tile ----
        float c[4][4];
        #pragma unroll
        for (int nt = 0; nt < 4; nt++){
            c[nt][0] = 0.f; c[nt][1] = 0.f; c[nt][2] = 0.f; c[nt][3] = 0.f;
        }
        #pragma unroll
        for (int kt = 0; kt < KT; kt++){
            uint32_t ko = (uint32_t)kt * 32u;
            uint32_t xh0[4], xh1[4], xl0[4], xl1[4];
            ldsm4(xh0, bh0 + ko); ldsm4(xh1, bh1 + ko);
            ldsm4(xl0, bl0 + ko); ldsm4(xl1, bl1 + ko);
            // nt0:{xh0[0],xh0[1]} nt1:{xh0[2],xh0[3]} nt2:{xh1[0],xh1[1]} nt3:{xh1[2],xh1[3]}
            mma16816(c[0], ahi[kt], xh0[0], xh0[1]);
            mma16816(c[1], ahi[kt], xh0[2], xh0[3]);
            mma16816(c[2], ahi[kt], xh1[0], xh1[1]);
            mma16816(c[3], ahi[kt], xh1[2], xh1[3]);
            mma16816(c[0], ahi[kt], xl0[0], xl0[1]);
            mma16816(c[1], ahi[kt], xl0[2], xl0[3]);
            mma16816(c[2], ahi[kt], xl1[0], xl1[1]);
            mma16816(c[3], ahi[kt], xl1[2], xl1[3]);
            mma16816(c[0], alo[kt], xh0[0], xh0[1]);
            mma16816(c[1], alo[kt], xh0[2], xh0[3]);
            mma16816(c[2], alo[kt], xh1[0], xh1[1]);
            mma16816(c[3], alo[kt], xh1[2], xh1[3]);
        }
        // ---- scatter C to gates[batch][gate] ----
        #pragma unroll
        for (int nt = 0; nt < 4; nt++){
            int col0 = nt*8 + tig*2;
            gates[col0*GSTRD + G0]           = c[nt][0];
            gates[(col0+1)*GSTRD + G0]       = c[nt][1];
            gates[col0*GSTRD + G0 + 8]       = c[nt][2];
            gates[(col0+1)*GSTRD + G0 + 8]   = c[nt][3];
        }
        __syncthreads();

        // ---- update: 4 cells (urow, j0..j0+3) ----
        {
            const float* gm = gates + urow*GSTRD;
            float4 gi = *(const float4*)&gm[j0];
            float4 gf = *(const float4*)&gm[64 + j0];
            float4 gg = *(const float4*)&gm[128 + j0];
            float4 go = *(const float4*)&gm[192 + j0];
            float4 bi = *(const float4*)&bias_s[j0];
            float4 bf = *(const float4*)&bias_s[64 + j0];
            float4 bg = *(const float4*)&bias_s[128 + j0];
            float4 bo = *(const float4*)&bias_s[192 + j0];
            float iv[4] = {gi.x+bi.x, gi.y+bi.y, gi.z+bi.z, gi.w+bi.w};
            float fv[4] = {gf.x+bf.x, gf.y+bf.y, gf.z+bf.z, gf.w+bf.w};
            float gv[4] = {gg.x+bg.x, gg.y+bg.y, gg.z+bg.z, gg.w+bg.w};
            float ov[4] = {go.x+bo.x, go.y+bo.y, go.z+bo.z, go.w+bo.w};
            float hv[4];
            #pragma unroll
            for (int q = 0; q < 4; q++){
                float cc = sig_(fv[q])*cst[q] + sig_(iv[q])*tanh_(gv[q]);
                cst[q] = cc;
                hv[q] = sig_(ov[q])*tanh_(cc);
            }
            // h -> fp16 hi/lo into X tile
            __half h0 = __float2half_rn(hv[0]), h1 = __float2half_rn(hv[1]);
            __half h2 = __float2half_rn(hv[2]), h3 = __float2half_rn(hv[3]);
            __half l0 = __float2half_rn(hv[0] - __half2float(h0));
            __half l1 = __float2half_rn(hv[1] - __half2float(h1));
            __half l2 = __float2half_rn(hv[2] - __half2float(h2));
            __half l3 = __float2half_rn(hv[3] - __half2float(h3));
            __half2* dh = (__half2*)&Bhi[urow*STRD + HOFF + j0];
            __half2* dl = (__half2*)&Blo[urow*STRD + HOFF + j0];
            dh[0] = __half2(h0, h1); dh[1] = __half2(h2, h3);
            dl[0] = __half2(l0, l1); dl[1] = __half2(l2, l3);

            if (ys)
                *(float4*)&ys[((size_t)t*B_ + row0 + urow)*H_ + j0] = make_float4(hv[0],hv[1],hv[2],hv[3]);
            if (hf && t == S_-1)
                *(float4*)&hf[(row0 + urow)*H_ + j0] = make_float4(hv[0],hv[1],hv[2],hv[3]);
        }
        if (t + 1 < S_) load_x(t + 1);
        __syncthreads();
    }
}

__global__ void __launch_bounds__(512, 1) lstm_l0(
    const float* __restrict__ c_wih, const float* __restrict__ c_whh,
    const float* __restrict__ c_bih, const float* __restrict__ c_bhh,
    const float* __restrict__ v_wih, const float* __restrict__ v_whh,
    const float* __restrict__ v_bih, const float* __restrict__ v_bhh)
{
    extern __shared__ char smem[];
    if (blockIdx.x < 64){
        lstm_stream<6, CC, 32>(smem, g_convout, g_ys_cnn, nullptr, blockIdx.x*32,
                               c_wih, c_whh, c_bih, c_bhh);
    } else {
        lstm_stream<5, DIN, 16>(smem, g_xT, g_ys_vq, nullptr, (blockIdx.x-64)*32,
                                v_wih, v_whh, v_bih, v_bhh);
    }
}

__global__ void __launch_bounds__(512, 1) lstm_l1(
    const float* __restrict__ c_wih, const float* __restrict__ c_whh,
    const float* __restrict__ c_bih, const float* __restrict__ c_bhh,
    const float* __restrict__ v_wih, const float* __restrict__ v_whh,
    const float* __restrict__ v_bih, const float* __restrict__ v_bhh)
{
    extern __shared__ char smem[];
    if (blockIdx.x < 64){
        lstm_stream<8, H_, 64>(smem, g_ys_cnn, nullptr, g_cnn_feat, blockIdx.x*32,
                               c_wih, c_whh, c_bih, c_bhh);
    } else {
        lstm_stream<8, H_, 64>(smem, g_ys_vq, nullptr, g_vq_hid, (blockIdx.x-64)*32,
                               v_wih, v_whh, v_bih, v_bhh);
    }
}

// ---------------- VQ epilogue ----------------
__global__ void zero_k(){
    int t = threadIdx.x;
    if (t < NEMB) g_counts[t] = 0;
    if (t == 0)   g_sqsum = 0.f;
}

__global__ void vq_final(const float* __restrict__ proj_w, const float* __restrict__ proj_b,
                         const float* __restrict__ codebook, float* __restrict__ out)
{
    __shared__ float pw[EDIM*H_];
    __shared__ float pb[EDIM];
    __shared__ float cb[NEMB*EDIM];
    __shared__ float cn2[NEMB];
    __shared__ float red[256];
    int tid = threadIdx.x;
    for (int i = tid; i < EDIM*H_;   i += 256) pw[i] = proj_w[i];
    for (int i = tid; i < NEMB*EDIM; i += 256) cb[i] = codebook[i];
    if (tid < EDIM) pb[tid] = proj_b[tid];
    __syncthreads();
    if (tid < NEMB){
        float s = 0.f;
        #pragma unroll
        for (int e = 0; e < EDIM; e++){ float v = cb[tid*EDIM + e]; s = fmaf(v, v, s); }
        cn2[tid] = s;
    }
    __syncthreads();

    int b = blockIdx.x*256 + tid;
    float h[H_];
    const float4* hp = (const float4*)&g_vq_hid[b*H_];
    #pragma unroll
    for (int i = 0; i < H_/4; i++){
        float4 v = hp[i]; h[4*i] = v.x; h[4*i+1] = v.y; h[4*i+2] = v.z; h[4*i+3] = v.w;
    }
    float p[EDIM]; float p2 = 0.f;
    #pragma unroll
    for (int e = 0; e < EDIM; e++){
        float a = pb[e];
        #pragma unroll
        for (int d = 0; d < H_; d++) a = fmaf(pw[e*H_ + d], h[d], a);
        p[e] = a; p2 = fmaf(a, a, p2);
    }
    int best = 0; float dmin = 3.4e38f;
    #pragma unroll 4
    for (int n = 0; n < NEMB; n++){
        float dot = 0.f;
        #pragma unroll
        for (int e = 0; e < EDIM; e++) dot = fmaf(cb[n*EDIM + e], p[e], dot);
        float d = p2 + cn2[n] - 2.f*dot;
        if (d < dmin){ dmin = d; best = n; }
    }
    float rs = 0.f;
    #pragma unroll
    for (int e = 0; e < EDIM; e++){ float r = cb[best*EDIM + e] - p[e]; rs = fmaf(r, r, rs); }
    red[tid] = rs;
    atomicAdd(&g_counts[best], 1);

    const float* cf = &g_cnn_feat[b*H_];
    float* o0 = out + (size_t)b*96;
    float* o1 = out + (size_t)B_*96 + (size_t)b*96;
    #pragma unroll
    for (int jj = 0; jj < H_; jj++){ float v = cf[jj]; o0[jj] = v; o1[jj] = v; }
    #pragma unroll
    for (int e = 0; e < EDIM; e++){ float v = cb[best*EDIM + e]; o0[H_+e] = v; o1[H_+e] = v; }

    __syncthreads();
    for (int st = 128; st > 0; st >>= 1){
        if (tid < st) red[tid] += red[tid + st];
        __syncthreads();
    }
    if (tid == 0) atomicAdd(&g_sqsum, red[0]);
}

__global__ void finalize_k(float* __restrict__ out){
    if (threadIdx.x == 0){
        float msq = g_sqsum / (float)(B_*EDIM);
        out[(size_t)2*B_*96]     = msq + 0.01f * msq;
        float ent = 0.f;
        for (int n = 0; n < NEMB; n++){
            float ap = (float)g_counts[n] / (float)B_;
            ent += ap * logf(ap + 1e-10f);
        }
        out[(size_t)2*B_*96 + 1] = expf(-ent);
    }
}

// ---------------- launch ----------------
extern "C" void kernel_launch(void* const* d_in, const int* in_sizes, int n_in,
                              void* d_out, int out_size)
{
    const float* x       = (const float*)d_in[0];
    const float* conv_w  = (const float*)d_in[1];
    const float* conv_b  = (const float*)d_in[2];
    const float* bn_g    = (const float*)d_in[3];
    const float* bn_b    = (const float*)d_in[4];
    const float* bn_m    = (const float*)d_in[5];
    const float* bn_v    = (const float*)d_in[6];
    const float* c0_wih  = (const float*)d_in[7];
    const float* c0_whh  = (const float*)d_in[8];
    const float* c0_bih  = (const float*)d_in[9];
    const float* c0_bhh  = (const float*)d_in[10];
    const float* c1_wih  = (const float*)d_in[11];
    const float* c1_whh  = (const float*)d_in[12];
    const float* c1_bih  = (const float*)d_in[13];
    const float* c1_bhh  = (const float*)d_in[14];
    const float* v0_wih  = (const float*)d_in[15];
    const float* v0_whh  = (const float*)d_in[16];
    const float* v0_bih  = (const float*)d_in[17];
    const float* v0_bhh  = (const float*)d_in[18];
    const float* v1_wih  = (const float*)d_in[19];
    const float* v1_whh  = (const float*)d_in[20];
    const float* v1_bih  = (const float*)d_in[21];
    const float* v1_bhh  = (const float*)d_in[22];
    const float* proj_w  = (const float*)d_in[23];
    const float* proj_b  = (const float*)d_in[24];
    const float* codebook= (const float*)d_in[25];
    float* out = (float*)d_out;

    cudaFuncSetAttribute(lstm_l0, cudaFuncAttributeMaxDynamicSharedMemorySize, SMEM_TOT);
    cudaFuncSetAttribute(lstm_l1, cudaFuncAttributeMaxDynamicSharedMemorySize, SMEM_TOT);

    prep_kernel<<<(B_*S_)/256, 256>>>(x, conv_w, conv_b, bn_g, bn_b, bn_m, bn_v);
    zero_k<<<1, 64>>>();
    lstm_l0<<<128, 512, SMEM_TOT>>>(c0_wih, c0_whh, c0_bih, c0_bhh,
                                    v0_wih, v0_whh, v0_bih, v0_bhh);
    lstm_l1<<<128, 512, SMEM_TOT>>>(c1_wih, c1_whh, c1_bih, c1_bhh,
                                    v1_wih, v1_whh, v1_bih, v1_bhh);
    vq_final<<<B_/256, 256>>>(proj_w, proj_b, codebook, out);
    finalize_k<<<1, 64>>>(out);
}

// round 9
// speedup vs baseline: 3.2186x; 1.5796x over previous
#include <cuda_runtime.h>
#include <cuda_fp16.h>
#include <cstdint>

#define B_   2048
#define S_   512
#define DIN  5
#define H_   64
#define CC   32
#define EDIM 32
#define NEMB 64

// ---------------- static device scratch ----------------
__device__ __align__(16) float g_convout[(size_t)S_*B_*CC];   // [S][B][32]
__device__ __align__(16) float g_xT[(size_t)S_*B_*8];         // [S][B][5] stride 5
__device__ __align__(16) float g_ys_cnn[(size_t)S_*B_*H_];
__device__ __align__(16) float g_ys_vq[(size_t)S_*B_*H_];
__device__ __align__(16) float g_cnn_feat[B_*H_];
__device__ __align__(16) float g_vq_hid[B_*H_];
__device__ float g_sqsum;
__device__ int   g_counts[NEMB];

// ---------------- helpers ----------------
__device__ __forceinline__ float sig_(float x){ return __fdividef(1.f, 1.f + __expf(-x)); }
__device__ __forceinline__ float tanh_(float x){ return __fdividef(2.f, 1.f + __expf(-2.f*x)) - 1.f; }

__device__ __forceinline__ uint32_t smem_u32(const void* p){
    uint32_t a; asm("{ .reg .u64 t; cvta.to.shared.u64 t, %1; cvt.u32.u64 %0, t; }" : "=r"(a) : "l"(p)); return a;
}
__device__ __forceinline__ void ldsm4(uint32_t* r, uint32_t addr){
    asm volatile("ldmatrix.sync.aligned.m8n8.x4.shared.b16 {%0,%1,%2,%3}, [%4];"
        : "=r"(r[0]), "=r"(r[1]), "=r"(r[2]), "=r"(r[3]) : "r"(addr));
}
__device__ __forceinline__ void mma16816(float* c, const uint32_t* a, uint32_t b0, uint32_t b1){
    asm volatile("mma.sync.aligned.m16n8k16.row.col.f32.f16.f16.f32 "
        "{%0,%1,%2,%3}, {%4,%5,%6,%7}, {%8,%9}, {%0,%1,%2,%3};"
        : "+f"(c[0]), "+f"(c[1]), "+f"(c[2]), "+f"(c[3])
        : "r"(a[0]), "r"(a[1]), "r"(a[2]), "r"(a[3]), "r"(b0), "r"(b1));
}

#define STRD   136       // halves per X/A row
#define HBSTR  68        // floats per hbuf row
// smem byte layout
#define OFF_B0   0       // X tile buf0: hi [32][136] (8704B) + lo (8704B)
#define B_LOB    8704    // lo byte offset within a buffer
#define OFF_B1   17408
#define OFF_HB0  34816   // h fp32 [32][68] = 8704B
#define OFF_HB1  43520
#define OFF_AHI  52224   // [256][136] halves = 69632B
#define OFF_ALO  121856
#define SMEM_TOT 191488

// ---------------- prep: conv1d + BN + ReLU + transpose ----------------
__global__ void prep_kernel(const float* __restrict__ x, const float* __restrict__ conv_w,
                            const float* __restrict__ conv_b, const float* __restrict__ bn_g,
                            const float* __restrict__ bn_b, const float* __restrict__ bn_m,
                            const float* __restrict__ bn_v)
{
    __shared__ float ws[CC*15];
    __shared__ float bs[CC];
    int tid = threadIdx.x;
    for (int idx = tid; idx < CC*15; idx += 256){
        int c = idx / 15;
        float sc = bn_g[c] * rsqrtf(bn_v[c] + 1e-5f);
        ws[idx] = conv_w[idx] * sc;
    }
    if (tid < CC){
        float sc = bn_g[tid] * rsqrtf(bn_v[tid] + 1e-5f);
        bs[tid] = (conv_b[tid] - bn_m[tid]) * sc + bn_b[tid];
    }
    __syncthreads();

    int gid = blockIdx.x * 256 + tid;   // gid = b*S + s
    int s = gid & (S_-1);
    size_t xb = (size_t)gid * DIN;
    int b = gid >> 9;
    float x0[DIN], xm[DIN], xp[DIN];
    #pragma unroll
    for (int i = 0; i < DIN; i++){
        x0[i] = x[xb + i];
        xm[i] = (s > 0)    ? x[xb - DIN + i] : 0.f;
        xp[i] = (s < S_-1) ? x[xb + DIN + i] : 0.f;
    }
    float o[CC];
    #pragma unroll
    for (int c = 0; c < CC; c++){
        float acc = bs[c];
        #pragma unroll
        for (int i = 0; i < DIN; i++){
            acc = fmaf(xm[i], ws[c*15 + i*3 + 0], acc);
            acc = fmaf(x0[i], ws[c*15 + i*3 + 1], acc);
            acc = fmaf(xp[i], ws[c*15 + i*3 + 2], acc);
        }
        o[c] = fmaxf(acc, 0.f);
    }
    float4* dst = (float4*)&g_convout[((size_t)s*B_ + b)*CC];
    #pragma unroll
    for (int c = 0; c < CC/4; c++) dst[c] = make_float4(o[4*c], o[4*c+1], o[4*c+2], o[4*c+3]);
    float* xt = &g_xT[((size_t)s*B_ + b)*DIN];
    #pragma unroll
    for (int i = 0; i < DIN; i++) xt[i] = x0[i];
}

// ---------------- HMMA split-fp16 LSTM stream, shfl gate-exchange ----------------
// 512 thr / 16 warps. Warp w owns cells jc in [4w,4w+4). A rows permuted so that
// warp-local row r: cell = 4w + ((r&7)>>1); gate = (r<8) ? (r&1 ? F : I) : (r&1 ? O : G).
// Thread gq then holds (I,G) [even gq] or (F,O) [odd gq] of cell 4w+(gq>>1); lane^4
// shuffle pairs them. One __syncthreads per step; X tile double-buffered.
template<int KT, int KIN, int HOFF>
__device__ void lstm_stream(char* smem, const float* __restrict__ in_seq,
                            float* __restrict__ ys, float* __restrict__ hf, int row0,
                            const float* __restrict__ wih, const float* __restrict__ whh,
                            const float* __restrict__ bih, const float* __restrict__ bhh)
{
    const int tid  = threadIdx.x;
    const int lane = tid & 31;
    const int w    = tid >> 5;
    constexpr int K = KT * 16;
    const uint32_t sbase = smem_u32(smem);

    __half* Ahi = (__half*)(smem + OFF_AHI);
    __half* Alo = (__half*)(smem + OFF_ALO);

    // ---- stage split weights with gate-row permutation ----
    for (int idx = tid; idx < 256*K; idx += 512){
        int m = idx / K, k = idx - m*K;
        int ww = m >> 4, r = m & 15;
        int jcell = 4*ww + ((r & 7) >> 1);
        int gate  = (r < 8) ? (r & 1) : 2 + (r & 1);
        int n = gate*64 + jcell;
        float v = 0.f;
        if (k < KIN)                          v = wih[n*KIN + k];
        else if (k >= HOFF && k < HOFF + H_)  v = whh[n*H_ + (k - HOFF)];
        __half hi = __float2half_rn(v);
        Ahi[m*STRD + k] = hi;
        Alo[m*STRD + k] = __float2half_rn(v - __half2float(hi));
    }
    // zero both X buffers (2*17408 B = 8704 words)
    for (int i = tid; i < 8704; i += 512) ((uint32_t*)smem)[i] = 0u;
    __syncthreads();

    // prime x(0) into buffer 0
    {
        __half* Bh = (__half*)(smem + OFF_B0);
        __half* Bl = (__half*)(smem + OFF_B0 + B_LOB);
        for (int idx = tid; idx < 32*KIN; idx += 512){
            int r = idx / KIN, k = idx - r*KIN;
            float v = in_seq[((size_t)row0 + r)*KIN + k];
            __half hi = __float2half_rn(v);
            Bh[r*STRD + k] = hi;
            Bl[r*STRD + k] = __float2half_rn(v - __half2float(hi));
        }
    }

    // ---- A-hi fragments resident in registers ----
    uint32_t ahi[KT][4];
    const int arow = (w << 4) + (lane & 7) + (((lane >> 3) & 1) << 3);
    const uint32_t abh = smem_u32(Ahi) + (uint32_t)(arow * STRD) * 2u;
    const uint32_t abl = smem_u32(Alo) + (uint32_t)(arow * STRD) * 2u;
    #pragma unroll
    for (int kt = 0; kt < KT; kt++)
        ldsm4(ahi[kt], abh + (uint32_t)(kt*16 + ((lane >> 4) << 3)) * 2u);

    // per-thread roles
    const int gq  = lane >> 2, tig = lane & 3;
    const int sel = gq & 1;                       // 0: holds I,G ; 1: holds F,O
    const int jc  = 4*w + (gq >> 1);              // hidden unit handled by this thread
    const float bI = bih[jc]      + bhh[jc];
    const float bF = bih[64+jc]   + bhh[64+jc];
    const float bG = bih[128+jc]  + bhh[128+jc];
    const float bO = bih[192+jc]  + bhh[192+jc];
    const int colbase = (sel ? 16 : 0) + 2*tig;
    const int bn = ((lane >> 4) << 3) + (lane & 7);
    const int bk = ((lane >> 3) & 1) << 3;
    const int frow = tid >> 4, fc0 = (tid & 15) << 2;   // ys flush mapping
    float cst[4] = {0.f, 0.f, 0.f, 0.f};
    __syncthreads();

    for (int t = 0; t < S_; t++){
        const int buf = t & 1;
        char* bcur  = smem + (buf ? OFF_B1 : OFF_B0);
        char* bnext = smem + (buf ? OFF_B0 : OFF_B1);
        float* hbW = (float*)(smem + (buf ? OFF_HB1 : OFF_HB0));

        // ---- stream ys(t-1) from hbuf (overlaps with GEMM) ----
        if (ys && t > 0){
            const float* hbR = (const float*)(smem + (buf ? OFF_HB0 : OFF_HB1));
            float4 v = *(const float4*)&hbR[frow*HBSTR + fc0];
            *(float4*)&ys[((size_t)(t-1)*B_ + row0 + frow)*H_ + fc0] = v;
        }

        // ---- prefetch x(t+1) into registers ----
        float xr0=0.f, xr1=0.f, xr2=0.f, xr3=0.f;
        if (t + 1 < S_){
            if (KIN == 64){
                const float4 q = *(const float4*)&in_seq[((size_t)(t+1)*B_ + row0 + (tid>>4))*64 + ((tid&15)<<2)];
                xr0=q.x; xr1=q.y; xr2=q.z; xr3=q.w;
            } else if (KIN == 32){
                const float2 q = *(const float2*)&in_seq[((size_t)(t+1)*B_ + row0 + (tid>>4))*32 + ((tid&15)<<1)];
                xr0=q.x; xr1=q.y;
            } else {
                if (tid < 32*KIN)
                    xr0 = in_seq[((size_t)(t+1)*B_ + row0 + tid/KIN)*KIN + (tid - (tid/KIN)*KIN)];
            }
        }

        // ---- GEMM ----
        float c[4][4];
        #pragma unroll
        for (int nt = 0; nt < 4; nt++){ c[nt][0]=0.f; c[nt][1]=0.f; c[nt][2]=0.f; c[nt][3]=0.f; }
        const uint32_t bh0 = sbase + (uint32_t)((buf ? OFF_B1 : OFF_B0)) + (uint32_t)(bn*STRD + bk)*2u;
        const uint32_t bh1 = bh0 + 16u*STRD*2u;
        const uint32_t bl0 = bh0 + B_LOB;
        const uint32_t bl1 = bh1 + B_LOB;
        #pragma unroll
        for (int kt = 0; kt < KT; kt++){
            const uint32_t ko = (uint32_t)kt * 32u;
            uint32_t xh0[4], xh1[4], xl0[4], xl1[4], alo[4];
            ldsm4(xh0, bh0 + ko); ldsm4(xh1, bh1 + ko);
            ldsm4(xl0, bl0 + ko); ldsm4(xl1, bl1 + ko);
            ldsm4(alo, abl + (uint32_t)(kt*16 + ((lane >> 4) << 3)) * 2u);
            mma16816(c[0], ahi[kt], xh0[0], xh0[1]);
            mma16816(c[1], ahi[kt], xh0[2], xh0[3]);
            mma16816(c[2], ahi[kt], xh1[0], xh1[1]);
            mma16816(c[3], ahi[kt], xh1[2], xh1[3]);
            mma16816(c[0], ahi[kt], xl0[0], xl0[1]);
            mma16816(c[1], ahi[kt], xl0[2], xl0[3]);
            mma16816(c[2], ahi[kt], xl1[0], xl1[1]);
            mma16816(c[3], ahi[kt], xl1[2], xl1[3]);
            mma16816(c[0], alo, xh0[0], xh0[1]);
            mma16816(c[1], alo, xh0[2], xh0[3]);
            mma16816(c[2], alo, xh1[0], xh1[1]);
            mma16816(c[3], alo, xh1[2], xh1[3]);
        }

        // ---- lane^4 exchange: pair (I,G) with (F,O) ----
        float xc[4][4];
        #pragma unroll
        for (int nt = 0; nt < 4; nt++)
            #pragma unroll
            for (int q = 0; q < 4; q++)
                xc[nt][q] = __shfl_xor_sync(0xffffffffu, c[nt][q], 4);

        // ---- update 4 cells: (u,p) -> col = colbase + 8u + p, unit jc ----
        __half* BhN = (__half*)bnext;
        __half* BlN = (__half*)(bnext + B_LOB);
        #pragma unroll
        for (int u = 0; u < 2; u++){
            #pragma unroll
            for (int p = 0; p < 2; p++){
                float own0 = sel ? c[u+2][p]    : c[u][p];
                float own2 = sel ? c[u+2][2+p]  : c[u][2+p];
                float oth0 = sel ? xc[u+2][p]   : xc[u][p];
                float oth2 = sel ? xc[u+2][2+p] : xc[u][2+p];
                float gi = (sel ? oth0 : own0) + bI;
                float gf = (sel ? own0 : oth0) + bF;
                float gg = (sel ? oth2 : own2) + bG;
                float go = (sel ? own2 : oth2) + bO;
                int li = u*2 + p;
                float cc = sig_(gf)*cst[li] + sig_(gi)*tanh_(gg);
                cst[li] = cc;
                float h = sig_(go)*tanh_(cc);
                int col = colbase + u*8 + p;
                __half hh = __float2half_rn(h);
                BhN[col*STRD + HOFF + jc] = hh;
                BlN[col*STRD + HOFF + jc] = __float2half_rn(h - __half2float(hh));
                if (ys) hbW[col*HBSTR + jc] = h;
                if (hf && t == S_-1) hf[(row0 + col)*H_ + jc] = h;
            }
        }

        // ---- store prefetched x(t+1) into next buffer ----
        if (t + 1 < S_){
            if (KIN == 64){
                int r = tid >> 4, c0 = (tid & 15) << 2;
                __half h0=__float2half_rn(xr0), h1=__float2half_rn(xr1);
                __half h2=__float2half_rn(xr2), h3=__float2half_rn(xr3);
                __half2 hiA(h0,h1), hiB(h2,h3);
                __half2 loA(__float2half_rn(xr0-__half2float(h0)), __float2half_rn(xr1-__half2float(h1)));
                __half2 loB(__float2half_rn(xr2-__half2float(h2)), __float2half_rn(xr3-__half2float(h3)));
                *(__half2*)&BhN[r*STRD + c0]     = hiA;
                *(__half2*)&BhN[r*STRD + c0 + 2] = hiB;
                *(__half2*)&BlN[r*STRD + c0]     = loA;
                *(__half2*)&BlN[r*STRD + c0 + 2] = loB;
            } else if (KIN == 32){
                int r = tid >> 4, c0 = (tid & 15) << 1;
                __half h0=__float2half_rn(xr0), h1=__float2half_rn(xr1);
                *(__half2*)&BhN[r*STRD + c0] = __half2(h0, h1);
                *(__half2*)&BlN[r*STRD + c0] =
                    __half2(__float2half_rn(xr0-__half2float(h0)), __float2half_rn(xr1-__half2float(h1)));
            } else {
                if (tid < 32*KIN){
                    int r = tid / KIN, k = tid - r*KIN;
                    __half h0 = __float2half_rn(xr0);
                    BhN[r*STRD + k] = h0;
                    BlN[r*STRD + k] = __float2half_rn(xr0 - __half2float(h0));
                }
            }
        }
        __syncthreads();
    }

    // final ys flush (step S-1 wrote hbuf[(S-1)&1] = HB1)
    if (ys){
        const float* hbR = (const float*)(smem + OFF_HB1);
        float4 v = *(const float4*)&hbR[frow*HBSTR + fc0];
        *(float4*)&ys[((size_t)(S_-1)*B_ + row0 + frow)*H_ + fc0] = v;
    }
}

__global__ void __launch_bounds__(512, 1) lstm_l0(
    const float* __restrict__ c_wih, const float* __restrict__ c_whh,
    const float* __restrict__ c_bih, const float* __restrict__ c_bhh,
    const float* __restrict__ v_wih, const float* __restrict__ v_whh,
    const float* __restrict__ v_bih, const float* __restrict__ v_bhh)
{
    extern __shared__ char smem[];
    if (blockIdx.x < 64)
        lstm_stream<6, CC, 32>(smem, g_convout, g_ys_cnn, nullptr, blockIdx.x*32,
                               c_wih, c_whh, c_bih, c_bhh);
    else
        lstm_stream<5, DIN, 16>(smem, g_xT, g_ys_vq, nullptr, (blockIdx.x-64)*32,
                                v_wih, v_whh, v_bih, v_bhh);
}

__global__ void __launch_bounds__(512, 1) lstm_l1(
    const float* __restrict__ c_wih, const float* __restrict__ c_whh,
    const float* __restrict__ c_bih, const float* __restrict__ c_bhh,
    const float* __restrict__ v_wih, const float* __restrict__ v_whh,
    const float* __restrict__ v_bih, const float* __restrict__ v_bhh)
{
    extern __shared__ char smem[];
    if (blockIdx.x < 64)
        lstm_stream<8, H_, 64>(smem, g_ys_cnn, nullptr, g_cnn_feat, blockIdx.x*32,
                               c_wih, c_whh, c_bih, c_bhh);
    else
        lstm_stream<8, H_, 64>(smem, g_ys_vq, nullptr, g_vq_hid, (blockIdx.x-64)*32,
                               v_wih, v_whh, v_bih, v_bhh);
}

// ---------------- VQ epilogue ----------------
__global__ void zero_k(){
    int t = threadIdx.x;
    if (t < NEMB) g_counts[t] = 0;
    if (t == 0)   g_sqsum = 0.f;
}

__global__ void vq_final(const float* __restrict__ proj_w, const float* __restrict__ proj_b,
                         const float* __restrict__ codebook, float* __restrict__ out)
{
    __shared__ float pw[EDIM*H_];
    __shared__ float pb[EDIM];
    __shared__ float cb[NEMB*EDIM];
    __shared__ float cn2[NEMB];
    __shared__ float red[256];
    int tid = threadIdx.x;
    for (int i = tid; i < EDIM*H_;   i += 256) pw[i] = proj_w[i];
    for (int i = tid; i < NEMB*EDIM; i += 256) cb[i] = codebook[i];
    if (tid < EDIM) pb[tid] = proj_b[tid];
    __syncthreads();
    if (tid < NEMB){
        float s = 0.f;
        #pragma unroll
        for (int e = 0; e < EDIM; e++){ float v = cb[tid*EDIM + e]; s = fmaf(v, v, s); }
        cn2[tid] = s;
    }
    __syncthreads();

    int b = blockIdx.x*256 + tid;
    float h[H_];
    const float4* hp = (const float4*)&g_vq_hid[b*H_];
    #pragma unroll
    for (int i = 0; i < H_/4; i++){
        float4 v = hp[i]; h[4*i] = v.x; h[4*i+1] = v.y; h[4*i+2] = v.z; h[4*i+3] = v.w;
    }
    float p[EDIM]; float p2 = 0.f;
    #pragma unroll
    for (int e = 0; e < EDIM; e++){
        float a = pb[e];
        #pragma unroll
        for (int d = 0; d < H_; d++) a = fmaf(pw[e*H_ + d], h[d], a);
        p[e] = a; p2 = fmaf(a, a, p2);
    }
    int best = 0; float dmin = 3.4e38f;
    #pragma unroll 4
    for (int n = 0; n < NEMB; n++){
        float dot = 0.f;
        #pragma unroll
        for (int e = 0; e < EDIM; e++) dot = fmaf(cb[n*EDIM + e], p[e], dot);
        float d = p2 + cn2[n] - 2.f*dot;
        if (d < dmin){ dmin = d; best = n; }
    }
    float rs = 0.f;
    #pragma unroll
    for (int e = 0; e < EDIM; e++){ float r = cb[best*EDIM + e] - p[e]; rs = fmaf(r, r, rs); }
    red[tid] = rs;
    atomicAdd(&g_counts[best], 1);

    const float* cf = &g_cnn_feat[b*H_];
    float* o0 = out + (size_t)b*96;
    float* o1 = out + (size_t)B_*96 + (size_t)b*96;
    #pragma unroll
    for (int jj = 0; jj < H_; jj++){ float v = cf[jj]; o0[jj] = v; o1[jj] = v; }
    #pragma unroll
    for (int e = 0; e < EDIM; e++){ float v = cb[best*EDIM + e]; o0[H_+e] = v; o1[H_+e] = v; }

    __syncthreads();
    for (int st = 128; st > 0; st >>= 1){
        if (tid < st) red[tid] += red[tid + st];
        __syncthreads();
    }
    if (tid == 0) atomicAdd(&g_sqsum, red[0]);
}

__global__ void finalize_k(float* __restrict__ out){
    if (threadIdx.x == 0){
        float msq = g_sqsum / (float)(B_*EDIM);
        out[(size_t)2*B_*96]     = msq + 0.01f * msq;
        float ent = 0.f;
        for (int n = 0; n < NEMB; n++){
            float ap = (float)g_counts[n] / (float)B_;
            ent += ap * logf(ap + 1e-10f);
        }
        out[(size_t)2*B_*96 + 1] = expf(-ent);
    }
}

// ---------------- launch ----------------
extern "C" void kernel_launch(void* const* d_in, const int* in_sizes, int n_in,
                              void* d_out, int out_size)
{
    const float* x       = (const float*)d_in[0];
    const float* conv_w  = (const float*)d_in[1];
    const float* conv_b  = (const float*)d_in[2];
    const float* bn_g    = (const float*)d_in[3];
    const float* bn_b    = (const float*)d_in[4];
    const float* bn_m    = (const float*)d_in[5];
    const float* bn_v    = (const float*)d_in[6];
    const float* c0_wih  = (const float*)d_in[7];
    const float* c0_whh  = (const float*)d_in[8];
    const float* c0_bih  = (const float*)d_in[9];
    const float* c0_bhh  = (const float*)d_in[10];
    const float* c1_wih  = (const float*)d_in[11];
    const float* c1_whh  = (const float*)d_in[12];
    const float* c1_bih  = (const float*)d_in[13];
    const float* c1_bhh  = (const float*)d_in[14];
    const float* v0_wih  = (const float*)d_in[15];
    const float* v0_whh  = (const float*)d_in[16];
    const float* v0_bih  = (const float*)d_in[17];
    const float* v0_bhh  = (const float*)d_in[18];
    const float* v1_wih  = (const float*)d_in[19];
    const float* v1_whh  = (const float*)d_in[20];
    const float* v1_bih  = (const float*)d_in[21];
    const float* v1_bhh  = (const float*)d_in[22];
    const float* proj_w  = (const float*)d_in[23];
    const float* proj_b  = (const float*)d_in[24];
    const float* codebook= (const float*)d_in[25];
    float* out = (float*)d_out;

    cudaFuncSetAttribute(lstm_l0, cudaFuncAttributeMaxDynamicSharedMemorySize, SMEM_TOT);
    cudaFuncSetAttribute(lstm_l1, cudaFuncAttributeMaxDynamicSharedMemorySize, SMEM_TOT);

    prep_kernel<<<(B_*S_)/256, 256>>>(x, conv_w, conv_b, bn_g, bn_b, bn_m, bn_v);
    zero_k<<<1, 64>>>();
    lstm_l0<<<128, 512, SMEM_TOT>>>(c0_wih, c0_whh, c0_bih, c0_bhh,
                                    v0_wih, v0_whh, v0_bih, v0_bhh);
    lstm_l1<<<128, 512, SMEM_TOT>>>(c1_wih, c1_whh, c1_bih, c1_bhh,
                                    v1_wih, v1_whh, v1_bih, v1_bhh);
    vq_final<<<B_/256, 256>>>(proj_w, proj_b, codebook, out);
    finalize_k<<<1, 64>>>(out);
}

// round 10
// speedup vs baseline: 3.4755x; 1.0798x over previous
#include <cuda_runtime.h>
#include <cuda_fp16.h>
#include <cstdint>

#define B_   2048
#define S_   512
#define DIN  5
#define H_   64
#define CC   32
#define EDIM 32
#define NEMB 64

// ---------------- static device scratch ----------------
__device__ __align__(16) float g_convout[(size_t)S_*B_*CC];   // [S][B][32]
__device__ __align__(16) float g_xT[(size_t)S_*B_*8];         // [S][B][5] stride 5
__device__ __align__(16) float g_ys_cnn[(size_t)S_*B_*H_];
__device__ __align__(16) float g_ys_vq[(size_t)S_*B_*H_];
__device__ __align__(16) float g_cnn_feat[B_*H_];
__device__ __align__(16) float g_vq_hid[B_*H_];
__device__ float g_sqsum;
__device__ int   g_counts[NEMB];

// ---------------- helpers ----------------
__device__ __forceinline__ float sig_(float x){ return __fdividef(1.f, 1.f + __expf(-x)); }
__device__ __forceinline__ float tanh_(float x){ return __fdividef(2.f, 1.f + __expf(-2.f*x)) - 1.f; }

__device__ __forceinline__ uint32_t smem_u32(const void* p){
    uint32_t a; asm("{ .reg .u64 t; cvta.to.shared.u64 t, %1; cvt.u32.u64 %0, t; }" : "=r"(a) : "l"(p)); return a;
}
__device__ __forceinline__ void ldsm4(uint32_t* r, uint32_t addr){
    asm volatile("ldmatrix.sync.aligned.m8n8.x4.shared.b16 {%0,%1,%2,%3}, [%4];"
        : "=r"(r[0]), "=r"(r[1]), "=r"(r[2]), "=r"(r[3]) : "r"(addr));
}
__device__ __forceinline__ void mma16816(float* c, const uint32_t* a, uint32_t b0, uint32_t b1){
    asm volatile("mma.sync.aligned.m16n8k16.row.col.f32.f16.f16.f32 "
        "{%0,%1,%2,%3}, {%4,%5,%6,%7}, {%8,%9}, {%0,%1,%2,%3};"
        : "+f"(c[0]), "+f"(c[1]), "+f"(c[2]), "+f"(c[3])
        : "r"(a[0]), "r"(a[1]), "r"(a[2]), "r"(a[3]), "r"(b0), "r"(b1));
}

#define STRD   136       // halves per X/A row
#define HBSTR  68        // floats per hbuf row
// smem byte layout
#define OFF_B0   0       // X tile buf0: hi [32][136] (8704B) + lo (8704B)
#define B_LOB    8704    // lo byte offset within a buffer
#define OFF_B1   17408
#define OFF_HB0  34816   // h fp32 [32][68] = 8704B
#define OFF_HB1  43520
#define OFF_AHI  52224   // [256][136] halves = 69632B
#define OFF_ALO  121856
#define SMEM_TOT 191488

// ---------------- prep: conv1d + BN + ReLU + transpose ----------------
__global__ void prep_kernel(const float* __restrict__ x, const float* __restrict__ conv_w,
                            const float* __restrict__ conv_b, const float* __restrict__ bn_g,
                            const float* __restrict__ bn_b, const float* __restrict__ bn_m,
                            const float* __restrict__ bn_v)
{
    __shared__ float ws[CC*15];
    __shared__ float bs[CC];
    int tid = threadIdx.x;
    for (int idx = tid; idx < CC*15; idx += 256){
        int c = idx / 15;
        float sc = bn_g[c] * rsqrtf(bn_v[c] + 1e-5f);
        ws[idx] = conv_w[idx] * sc;
    }
    if (tid < CC){
        float sc = bn_g[tid] * rsqrtf(bn_v[tid] + 1e-5f);
        bs[tid] = (conv_b[tid] - bn_m[tid]) * sc + bn_b[tid];
    }
    __syncthreads();

    int gid = blockIdx.x * 256 + tid;   // gid = b*S + s
    int s = gid & (S_-1);
    size_t xb = (size_t)gid * DIN;
    int b = gid >> 9;
    float x0[DIN], xm[DIN], xp[DIN];
    #pragma unroll
    for (int i = 0; i < DIN; i++){
        x0[i] = x[xb + i];
        xm[i] = (s > 0)    ? x[xb - DIN + i] : 0.f;
        xp[i] = (s < S_-1) ? x[xb + DIN + i] : 0.f;
    }
    float o[CC];
    #pragma unroll
    for (int c = 0; c < CC; c++){
        float acc = bs[c];
        #pragma unroll
        for (int i = 0; i < DIN; i++){
            acc = fmaf(xm[i], ws[c*15 + i*3 + 0], acc);
            acc = fmaf(x0[i], ws[c*15 + i*3 + 1], acc);
            acc = fmaf(xp[i], ws[c*15 + i*3 + 2], acc);
        }
        o[c] = fmaxf(acc, 0.f);
    }
    float4* dst = (float4*)&g_convout[((size_t)s*B_ + b)*CC];
    #pragma unroll
    for (int c = 0; c < CC/4; c++) dst[c] = make_float4(o[4*c], o[4*c+1], o[4*c+2], o[4*c+3]);
    float* xt = &g_xT[((size_t)s*B_ + b)*DIN];
    #pragma unroll
    for (int i = 0; i < DIN; i++) xt[i] = x0[i];
}

// ---------------- HMMA split-fp16 LSTM stream, x-GEMM/update overlap ----------------
// 512 thr / 16 warps. Same A-row permutation + lane^4 shfl gate exchange as before.
// K tiles: x-part = tiles [0,XT) (k in [0,16*XT)); h-part = tiles [XT,XT+HT) (k in [HOFF,HOFF+64)),
// HOFF = 16*XT. Per step: h-part MMA completes C for step t; after the mid barrier the x-part
// MMAs for step t+1 are issued into the other accumulator and retire under the MUFU update.
template<int XT, int HT, int KIN>
__device__ void lstm_stream(char* smem, const float* __restrict__ in_seq,
                            float* __restrict__ ys, float* __restrict__ hf, int row0,
                            const float* __restrict__ wih, const float* __restrict__ whh,
                            const float* __restrict__ bih, const float* __restrict__ bhh)
{
    const int tid  = threadIdx.x;
    const int lane = tid & 31;
    const int w    = tid >> 5;
    constexpr int KT   = XT + HT;
    constexpr int K    = KT * 16;
    constexpr int HOFF = XT * 16;
    const uint32_t sbase = smem_u32(smem);

    __half* Ahi = (__half*)(smem + OFF_AHI);
    __half* Alo = (__half*)(smem + OFF_ALO);

    // ---- stage split weights with gate-row permutation ----
    for (int idx = tid; idx < 256*K; idx += 512){
        int m = idx / K, k = idx - m*K;
        int ww = m >> 4, r = m & 15;
        int jcell = 4*ww + ((r & 7) >> 1);
        int gate  = (r < 8) ? (r & 1) : 2 + (r & 1);
        int n = gate*64 + jcell;
        float v = 0.f;
        if (k < KIN)                          v = wih[n*KIN + k];
        else if (k >= HOFF && k < HOFF + H_)  v = whh[n*H_ + (k - HOFF)];
        __half hi = __float2half_rn(v);
        Ahi[m*STRD + k] = hi;
        Alo[m*STRD + k] = __float2half_rn(v - __half2float(hi));
    }
    // zero both X buffers
    for (int i = tid; i < 8704; i += 512) ((uint32_t*)smem)[i] = 0u;
    __syncthreads();

    // ---- A-hi fragments resident in registers ----
    uint32_t ahi[KT][4];
    const int arow = (w << 4) + (lane & 7) + (((lane >> 3) & 1) << 3);
    const uint32_t abh = smem_u32(Ahi) + (uint32_t)(arow * STRD) * 2u;
    const uint32_t abl = smem_u32(Alo) + (uint32_t)(arow * STRD) * 2u;
    #pragma unroll
    for (int kt = 0; kt < KT; kt++)
        ldsm4(ahi[kt], abh + (uint32_t)(kt*16 + ((lane >> 4) << 3)) * 2u);

    // per-thread roles
    const int gq  = lane >> 2, tig = lane & 3;
    const int sel = gq & 1;
    const int jc  = 4*w + (gq >> 1);
    const float bI = bih[jc]      + bhh[jc];
    const float bF = bih[64+jc]   + bhh[64+jc];
    const float bG = bih[128+jc]  + bhh[128+jc];
    const float bO = bih[192+jc]  + bhh[192+jc];
    const int colbase = (sel ? 16 : 0) + 2*tig;
    const int bn = ((lane >> 4) << 3) + (lane & 7);
    const int bk = ((lane >> 3) & 1) << 3;
    const int frow = tid >> 4, fc0 = (tid & 15) << 2;
    float cst[4] = {0.f, 0.f, 0.f, 0.f};

    float xr0=0.f, xr1=0.f, xr2=0.f, xr3=0.f;

    auto xpref = [&](int t){
        if (KIN == 64){
            const float4 q = *(const float4*)&in_seq[((size_t)t*B_ + row0 + (tid>>4))*64 + ((tid&15)<<2)];
            xr0=q.x; xr1=q.y; xr2=q.z; xr3=q.w;
        } else if (KIN == 32){
            const float2 q = *(const float2*)&in_seq[((size_t)t*B_ + row0 + (tid>>4))*32 + ((tid&15)<<1)];
            xr0=q.x; xr1=q.y;
        } else {
            if (tid < 32*KIN)
                xr0 = in_seq[((size_t)t*B_ + row0 + tid/KIN)*KIN + (tid - (tid/KIN)*KIN)];
        }
    };
    auto xstore = [&](char* bdst){
        __half* BhN = (__half*)bdst;
        __half* BlN = (__half*)(bdst + B_LOB);
        if (KIN == 64){
            int r = tid >> 4, c0 = (tid & 15) << 2;
            __half h0=__float2half_rn(xr0), h1=__float2half_rn(xr1);
            __half h2=__float2half_rn(xr2), h3=__float2half_rn(xr3);
            *(__half2*)&BhN[r*STRD + c0]     = __half2(h0,h1);
            *(__half2*)&BhN[r*STRD + c0 + 2] = __half2(h2,h3);
            *(__half2*)&BlN[r*STRD + c0]     =
                __half2(__float2half_rn(xr0-__half2float(h0)), __float2half_rn(xr1-__half2float(h1)));
            *(__half2*)&BlN[r*STRD + c0 + 2] =
                __half2(__float2half_rn(xr2-__half2float(h2)), __float2half_rn(xr3-__half2float(h3)));
        } else if (KIN == 32){
            int r = tid >> 4, c0 = (tid & 15) << 1;
            __half h0=__float2half_rn(xr0), h1=__float2half_rn(xr1);
            *(__half2*)&BhN[r*STRD + c0] = __half2(h0, h1);
            *(__half2*)&BlN[r*STRD + c0] =
                __half2(__float2half_rn(xr0-__half2float(h0)), __float2half_rn(xr1-__half2float(h1)));
        } else {
            if (tid < 32*KIN){
                int r = tid / KIN, k = tid - r*KIN;
                __half h0 = __float2half_rn(xr0);
                BhN[r*STRD + k] = h0;
                BlN[r*STRD + k] = __float2half_rn(xr0 - __half2float(h0));
            }
        }
    };
    auto mma12 = [&](float (&c)[4][4], const uint32_t* ah, const uint32_t* al,
                     const uint32_t* xh0, const uint32_t* xh1,
                     const uint32_t* xl0, const uint32_t* xl1){
        mma16816(c[0], ah, xh0[0], xh0[1]);
        mma16816(c[1], ah, xh0[2], xh0[3]);
        mma16816(c[2], ah, xh1[0], xh1[1]);
        mma16816(c[3], ah, xh1[2], xh1[3]);
        mma16816(c[0], ah, xl0[0], xl0[1]);
        mma16816(c[1], ah, xl0[2], xl0[3]);
        mma16816(c[2], ah, xl1[0], xl1[1]);
        mma16816(c[3], ah, xl1[2], xl1[3]);
        mma16816(c[0], al, xh0[0], xh0[1]);
        mma16816(c[1], al, xh0[2], xh0[3]);
        mma16816(c[2], al, xh1[0], xh1[1]);
        mma16816(c[3], al, xh1[2], xh1[3]);
    };
    auto xpart = [&](float (&cA)[4][4], uint32_t boff){
        #pragma unroll
        for (int nt = 0; nt < 4; nt++){ cA[nt][0]=0.f; cA[nt][1]=0.f; cA[nt][2]=0.f; cA[nt][3]=0.f; }
        const uint32_t h0 = sbase + boff + (uint32_t)(bn*STRD + bk)*2u;
        const uint32_t h1 = h0 + 16u*STRD*2u;
        const uint32_t l0 = h0 + B_LOB, l1 = h1 + B_LOB;
        #pragma unroll
        for (int kt = 0; kt < XT; kt++){
            const uint32_t ko = (uint32_t)kt * 32u;
            uint32_t xh0[4], xh1[4], xl0[4], xl1[4], alo[4];
            ldsm4(xh0, h0 + ko); ldsm4(xh1, h1 + ko);
            ldsm4(xl0, l0 + ko); ldsm4(xl1, l1 + ko);
            ldsm4(alo, abl + (uint32_t)(kt*16 + ((lane >> 4) << 3)) * 2u);
            mma12(cA, ahi[kt], alo, xh0, xh1, xl0, xl1);
        }
    };

    // ---- prime: x(0) -> buf0, xr <- x(1), c0 <- x-part(t=0) ----
    {
        __half* Bh = (__half*)(smem + OFF_B0);
        __half* Bl = (__half*)(smem + OFF_B0 + B_LOB);
        for (int idx = tid; idx < 32*KIN; idx += 512){
            int r = idx / KIN, k = idx - r*KIN;
            float v = in_seq[((size_t)row0 + r)*KIN + k];
            __half hi = __float2half_rn(v);
            Bh[r*STRD + k] = hi;
            Bl[r*STRD + k] = __float2half_rn(v - __half2float(hi));
        }
    }
    xpref(1);
    __syncthreads();
    float c0[4][4], c1[4][4];
    xpart(c0, OFF_B0);

    auto stepf = [&](int t, float (&cU)[4][4], float (&cA)[4][4]){
        const int p = t & 1;
        const uint32_t curoff = p ? OFF_B1 : OFF_B0;
        const uint32_t nxtoff = p ? OFF_B0 : OFF_B1;
        char* bnext = smem + nxtoff;
        float* hbW = (float*)(smem + (p ? OFF_HB1 : OFF_HB0));

        // stream ys(t-1) (overlaps h-part GEMM)
        if (ys && t > 0){
            const float* hbR = (const float*)(smem + (p ? OFF_HB0 : OFF_HB1));
            float4 v = *(const float4*)&hbR[frow*HBSTR + fc0];
            *(float4*)&ys[((size_t)(t-1)*B_ + row0 + frow)*H_ + fc0] = v;
        }

        // ---- h-part GEMM for step t ----
        {
            const uint32_t h0 = sbase + curoff + (uint32_t)(bn*STRD + bk)*2u;
            const uint32_t h1 = h0 + 16u*STRD*2u;
            const uint32_t l0 = h0 + B_LOB, l1 = h1 + B_LOB;
            #pragma unroll
            for (int kt = 0; kt < HT; kt++){
                const int kk = XT + kt;
                const uint32_t ko = (uint32_t)kk * 32u;
                uint32_t xh0[4], xh1[4], xl0[4], xl1[4], alo[4];
                ldsm4(xh0, h0 + ko); ldsm4(xh1, h1 + ko);
                ldsm4(xl0, l0 + ko); ldsm4(xl1, l1 + ko);
                ldsm4(alo, abl + (uint32_t)(kk*16 + ((lane >> 4) << 3)) * 2u);
                mma12(cU, ahi[kk], alo, xh0, xh1, xl0, xl1);
            }
        }

        // ---- lane^4 exchange ----
        float xc[4][4];
        #pragma unroll
        for (int nt = 0; nt < 4; nt++)
            #pragma unroll
            for (int q = 0; q < 4; q++)
                xc[nt][q] = __shfl_xor_sync(0xffffffffu, cU[nt][q], 4);

        // ---- publish x(t+1) to next buffer, then mid barrier ----
        if (t + 1 < S_) xstore(bnext);
        __syncthreads();

        // ---- issue x-part GEMM for t+1 (retires under the MUFU update below) ----
        if (t + 1 < S_) xpart(cA, nxtoff);
        if (t + 2 < S_) xpref(t + 2);

        // ---- update 4 cells ----
        __half* BhN = (__half*)bnext;
        __half* BlN = (__half*)(bnext + B_LOB);
        #pragma unroll
        for (int u = 0; u < 2; u++){
            #pragma unroll
            for (int pp = 0; pp < 2; pp++){
                float own0 = sel ? cU[u+2][pp]    : cU[u][pp];
                float own2 = sel ? cU[u+2][2+pp]  : cU[u][2+pp];
                float oth0 = sel ? xc[u+2][pp]    : xc[u][pp];
                float oth2 = sel ? xc[u+2][2+pp]  : xc[u][2+pp];
                float gi = (sel ? oth0 : own0) + bI;
                float gf = (sel ? own0 : oth0) + bF;
                float gg = (sel ? oth2 : own2) + bG;
                float go = (sel ? own2 : oth2) + bO;
                int li = u*2 + pp;
                float cc = sig_(gf)*cst[li] + sig_(gi)*tanh_(gg);
                cst[li] = cc;
                float h = sig_(go)*tanh_(cc);
                int col = colbase + u*8 + pp;
                __half hh = __float2half_rn(h);
                BhN[col*STRD + HOFF + jc] = hh;
                BlN[col*STRD + HOFF + jc] = __float2half_rn(h - __half2float(hh));
                if (ys) hbW[col*HBSTR + jc] = h;
                if (hf && t == S_-1) hf[(row0 + col)*H_ + jc] = h;
            }
        }
        __syncthreads();
    };

    for (int t = 0; t < S_; t += 2){
        stepf(t,     c0, c1);
        stepf(t + 1, c1, c0);
    }

    // final ys flush (step S-1 wrote hb[(S-1)&1] = HB1)
    if (ys){
        const float* hbR = (const float*)(smem + OFF_HB1);
        float4 v = *(const float4*)&hbR[frow*HBSTR + fc0];
        *(float4*)&ys[((size_t)(S_-1)*B_ + row0 + frow)*H_ + fc0] = v;
    }
}

__global__ void __launch_bounds__(512, 1) lstm_l0(
    const float* __restrict__ c_wih, const float* __restrict__ c_whh,
    const float* __restrict__ c_bih, const float* __restrict__ c_bhh,
    const float* __restrict__ v_wih, const float* __restrict__ v_whh,
    const float* __restrict__ v_bih, const float* __restrict__ v_bhh)
{
    extern __shared__ char smem[];
    if (blockIdx.x < 64)
        lstm_stream<2, 4, CC>(smem, g_convout, g_ys_cnn, nullptr, blockIdx.x*32,
                              c_wih, c_whh, c_bih, c_bhh);
    else
        lstm_stream<1, 4, DIN>(smem, g_xT, g_ys_vq, nullptr, (blockIdx.x-64)*32,
                               v_wih, v_whh, v_bih, v_bhh);
}

__global__ void __launch_bounds__(512, 1) lstm_l1(
    const float* __restrict__ c_wih, const float* __restrict__ c_whh,
    const float* __restrict__ c_bih, const float* __restrict__ c_bhh,
    const float* __restrict__ v_wih, const float* __restrict__ v_whh,
    const float* __restrict__ v_bih, const float* __restrict__ v_bhh)
{
    extern __shared__ char smem[];
    if (blockIdx.x < 64)
        lstm_stream<4, 4, H_>(smem, g_ys_cnn, nullptr, g_cnn_feat, blockIdx.x*32,
                              c_wih, c_whh, c_bih, c_bhh);
    else
        lstm_stream<4, 4, H_>(smem, g_ys_vq, nullptr, g_vq_hid, (blockIdx.x-64)*32,
                              v_wih, v_whh, v_bih, v_bhh);
}

// ---------------- VQ epilogue ----------------
__global__ void zero_k(){
    int t = threadIdx.x;
    if (t < NEMB) g_counts[t] = 0;
    if (t == 0)   g_sqsum = 0.f;
}

__global__ void vq_final(const float* __restrict__ proj_w, const float* __restrict__ proj_b,
                         const float* __restrict__ codebook, float* __restrict__ out)
{
    __shared__ float pw[EDIM*H_];
    __shared__ float pb[EDIM];
    __shared__ float cb[NEMB*EDIM];
    __shared__ float cn2[NEMB];
    __shared__ float red[256];
    int tid = threadIdx.x;
    for (int i = tid; i < EDIM*H_;   i += 256) pw[i] = proj_w[i];
    for (int i = tid; i < NEMB*EDIM; i += 256) cb[i] = codebook[i];
    if (tid < EDIM) pb[tid] = proj_b[tid];
    __syncthreads();
    if (tid < NEMB){
        float s = 0.f;
        #pragma unroll
        for (int e = 0; e < EDIM; e++){ float v = cb[tid*EDIM + e]; s = fmaf(v, v, s); }
        cn2[tid] = s;
    }
    __syncthreads();

    int b = blockIdx.x*256 + tid;
    float h[H_];
    const float4* hp = (const float4*)&g_vq_hid[b*H_];
    #pragma unroll
    for (int i = 0; i < H_/4; i++){
        float4 v = hp[i]; h[4*i] = v.x; h[4*i+1] = v.y; h[4*i+2] = v.z; h[4*i+3] = v.w;
    }
    float p[EDIM]; float p2 = 0.f;
    #pragma unroll
    for (int e = 0; e < EDIM; e++){
        float a = pb[e];
        #pragma unroll
        for (int d = 0; d < H_; d++) a = fmaf(pw[e*H_ + d], h[d], a);
        p[e] = a; p2 = fmaf(a, a, p2);
    }
    int best = 0; float dmin = 3.4e38f;
    #pragma unroll 4
    for (int n = 0; n < NEMB; n++){
        float dot = 0.f;
        #pragma unroll
        for (int e = 0; e < EDIM; e++) dot = fmaf(cb[n*EDIM + e], p[e], dot);
        float d = p2 + cn2[n] - 2.f*dot;
        if (d < dmin){ dmin = d; best = n; }
    }
    float rs = 0.f;
    #pragma unroll
    for (int e = 0; e < EDIM; e++){ float r = cb[best*EDIM + e] - p[e]; rs = fmaf(r, r, rs); }
    red[tid] = rs;
    atomicAdd(&g_counts[best], 1);

    const float* cf = &g_cnn_feat[b*H_];
    float* o0 = out + (size_t)b*96;
    float* o1 = out + (size_t)B_*96 + (size_t)b*96;
    #pragma unroll
    for (int jj = 0; jj < H_; jj++){ float v = cf[jj]; o0[jj] = v; o1[jj] = v; }
    #pragma unroll
    for (int e = 0; e < EDIM; e++){ float v = cb[best*EDIM + e]; o0[H_+e] = v; o1[H_+e] = v; }

    __syncthreads();
    for (int st = 128; st > 0; st >>= 1){
        if (tid < st) red[tid] += red[tid + st];
        __syncthreads();
    }
    if (tid == 0) atomicAdd(&g_sqsum, red[0]);
}

__global__ void finalize_k(float* __restrict__ out){
    if (threadIdx.x == 0){
        float msq = g_sqsum / (float)(B_*EDIM);
        out[(size_t)2*B_*96]     = msq + 0.01f * msq;
        float ent = 0.f;
        for (int n = 0; n < NEMB; n++){
            float ap = (float)g_counts[n] / (float)B_;
            ent += ap * logf(ap + 1e-10f);
        }
        out[(size_t)2*B_*96 + 1] = expf(-ent);
    }
}

// ---------------- launch ----------------
extern "C" void kernel_launch(void* const* d_in, const int* in_sizes, int n_in,
                              void* d_out, int out_size)
{
    const float* x       = (const float*)d_in[0];
    const float* conv_w  = (const float*)d_in[1];
    const float* conv_b  = (const float*)d_in[2];
    const float* bn_g    = (const float*)d_in[3];
    const float* bn_b    = (const float*)d_in[4];
    const float* bn_m    = (const float*)d_in[5];
    const float* bn_v    = (const float*)d_in[6];
    const float* c0_wih  = (const float*)d_in[7];
    const float* c0_whh  = (const float*)d_in[8];
    const float* c0_bih  = (const float*)d_in[9];
    const float* c0_bhh  = (const float*)d_in[10];
    const float* c1_wih  = (const float*)d_in[11];
    const float* c1_whh  = (const float*)d_in[12];
    const float* c1_bih  = (const float*)d_in[13];
    const float* c1_bhh  = (const float*)d_in[14];
    const float* v0_wih  = (const float*)d_in[15];
    const float* v0_whh  = (const float*)d_in[16];
    const float* v0_bih  = (const float*)d_in[17];
    const float* v0_bhh  = (const float*)d_in[18];
    const float* v1_wih  = (const float*)d_in[19];
    const float* v1_whh  = (const float*)d_in[20];
    const float* v1_bih  = (const float*)d_in[21];
    const float* v1_bhh  = (const float*)d_in[22];
    const float* proj_w  = (const float*)d_in[23];
    const float* proj_b  = (const float*)d_in[24];
    const float* codebook= (const float*)d_in[25];
    float* out = (float*)d_out;

    cudaFuncSetAttribute(lstm_l0, cudaFuncAttributeMaxDynamicSharedMemorySize, SMEM_TOT);
    cudaFuncSetAttribute(lstm_l1, cudaFuncAttributeMaxDynamicSharedMemorySize, SMEM_TOT);

    prep_kernel<<<(B_*S_)/256, 256>>>(x, conv_w, conv_b, bn_g, bn_b, bn_m, bn_v);
    zero_k<<<1, 64>>>();
    lstm_l0<<<128, 512, SMEM_TOT>>>(c0_wih, c0_whh, c0_bih, c0_bhh,
                                    v0_wih, v0_whh, v0_bih, v0_bhh);
    lstm_l1<<<128, 512, SMEM_TOT>>>(c1_wih, c1_whh, c1_bih, c1_bhh,
                                    v1_wih, v1_whh, v1_bih, v1_bhh);
    vq_final<<<B_/256, 256>>>(proj_w, proj_b, codebook, out);
    finalize_k<<<1, 64>>>(out);
}

// round 11
// speedup vs baseline: 3.6812x; 1.0592x over previous
#include <cuda_runtime.h>
#include <cuda_fp16.h>
#include <cstdint>

#define B_   2048
#define S_   512
#define DIN  5
#define H_   64
#define CC   32
#define EDIM 32
#define NEMB 64

// ---------------- static device scratch ----------------
__device__ __align__(16) float g_convout[(size_t)S_*B_*CC];   // [S][B][32]
__device__ __align__(16) float g_xT[(size_t)S_*B_*8];         // [S][B][5] stride 5
__device__ __align__(16) float g_ys_cnn[(size_t)S_*B_*H_];
__device__ __align__(16) float g_ys_vq[(size_t)S_*B_*H_];
__device__ __align__(16) float g_cnn_feat[B_*H_];
__device__ __align__(16) float g_vq_hid[B_*H_];
__device__ float g_sqsum;
__device__ int   g_counts[NEMB];

// ---------------- helpers ----------------
__device__ __forceinline__ float tanhapx(float x){
    float y; asm("tanh.approx.f32 %0, %1;" : "=f"(y) : "f"(x)); return y;
}
__device__ __forceinline__ float sig_a(float x){ return fmaf(0.5f, tanhapx(0.5f*x), 0.5f); }
__device__ __forceinline__ float tanh_(float x){ return __fdividef(2.f, 1.f + __expf(-2.f*x)) - 1.f; }
__device__ __forceinline__ float sig_(float x){ return __fdividef(1.f, 1.f + __expf(-x)); }

__device__ __forceinline__ uint32_t smem_u32(const void* p){
    uint32_t a; asm("{ .reg .u64 t; cvta.to.shared.u64 t, %1; cvt.u32.u64 %0, t; }" : "=r"(a) : "l"(p)); return a;
}
__device__ __forceinline__ void ldsm4(uint32_t* r, uint32_t addr){
    asm volatile("ldmatrix.sync.aligned.m8n8.x4.shared.b16 {%0,%1,%2,%3}, [%4];"
        : "=r"(r[0]), "=r"(r[1]), "=r"(r[2]), "=r"(r[3]) : "r"(addr));
}
__device__ __forceinline__ void mma16816(float* c, const uint32_t* a, uint32_t b0, uint32_t b1){
    asm volatile("mma.sync.aligned.m16n8k16.row.col.f32.f16.f16.f32 "
        "{%0,%1,%2,%3}, {%4,%5,%6,%7}, {%8,%9}, {%0,%1,%2,%3};"
        : "+f"(c[0]), "+f"(c[1]), "+f"(c[2]), "+f"(c[3])
        : "r"(a[0]), "r"(a[1]), "r"(a[2]), "r"(a[3]), "r"(b0), "r"(b1));
}

#define STRD   136       // halves per X/A row
#define HBSTR  68        // floats per hbuf row
// smem byte layout
#define OFF_B0   0       // X tile buf0: hi [32][136] (8704B) + lo (8704B)
#define B_LOB    8704    // lo byte offset within a buffer
#define OFF_B1   17408
#define OFF_HB0  34816   // h fp32 [32][68] = 8704B
#define OFF_HB1  43520
#define OFF_AHI  52224   // [256][136] halves = 69632B
#define OFF_ALO  121856
#define SMEM_TOT 191488

// ---------------- prep: conv1d + BN + ReLU + transpose ----------------
__global__ void prep_kernel(const float* __restrict__ x, const float* __restrict__ conv_w,
                            const float* __restrict__ conv_b, const float* __restrict__ bn_g,
                            const float* __restrict__ bn_b, const float* __restrict__ bn_m,
                            const float* __restrict__ bn_v)
{
    __shared__ float ws[CC*15];
    __shared__ float bs[CC];
    int tid = threadIdx.x;
    for (int idx = tid; idx < CC*15; idx += 256){
        int c = idx / 15;
        float sc = bn_g[c] * rsqrtf(bn_v[c] + 1e-5f);
        ws[idx] = conv_w[idx] * sc;
    }
    if (tid < CC){
        float sc = bn_g[tid] * rsqrtf(bn_v[tid] + 1e-5f);
        bs[tid] = (conv_b[tid] - bn_m[tid]) * sc + bn_b[tid];
    }
    __syncthreads();

    int gid = blockIdx.x * 256 + tid;   // gid = b*S + s
    int s = gid & (S_-1);
    size_t xb = (size_t)gid * DIN;
    int b = gid >> 9;
    float x0[DIN], xm[DIN], xp[DIN];
    #pragma unroll
    for (int i = 0; i < DIN; i++){
        x0[i] = x[xb + i];
        xm[i] = (s > 0)    ? x[xb - DIN + i] : 0.f;
        xp[i] = (s < S_-1) ? x[xb + DIN + i] : 0.f;
    }
    float o[CC];
    #pragma unroll
    for (int c = 0; c < CC; c++){
        float acc = bs[c];
        #pragma unroll
        for (int i = 0; i < DIN; i++){
            acc = fmaf(xm[i], ws[c*15 + i*3 + 0], acc);
            acc = fmaf(x0[i], ws[c*15 + i*3 + 1], acc);
            acc = fmaf(xp[i], ws[c*15 + i*3 + 2], acc);
        }
        o[c] = fmaxf(acc, 0.f);
    }
    float4* dst = (float4*)&g_convout[((size_t)s*B_ + b)*CC];
    #pragma unroll
    for (int c = 0; c < CC/4; c++) dst[c] = make_float4(o[4*c], o[4*c+1], o[4*c+2], o[4*c+3]);
    float* xt = &g_xT[((size_t)s*B_ + b)*DIN];
    #pragma unroll
    for (int i = 0; i < DIN; i++) xt[i] = x0[i];
}

// ---------------- HMMA split-fp16 LSTM stream, x-GEMM/update overlap ----------------
// 512 thr / 16 warps. A rows permuted; lane^4 shfl exchanges exactly the half of C
// each partner needs (8 values). x-part GEMM of step t+1 retires under the update.
template<int XT, int HT, int KIN>
__device__ void lstm_stream(char* smem, const float* __restrict__ in_seq,
                            float* __restrict__ ys, float* __restrict__ hf, int row0,
                            const float* __restrict__ wih, const float* __restrict__ whh,
                            const float* __restrict__ bih, const float* __restrict__ bhh)
{
    const int tid  = threadIdx.x;
    const int lane = tid & 31;
    const int w    = tid >> 5;
    constexpr int KT   = XT + HT;
    constexpr int K    = KT * 16;
    constexpr int HOFF = XT * 16;
    const uint32_t sbase = smem_u32(smem);

    __half* Ahi = (__half*)(smem + OFF_AHI);
    __half* Alo = (__half*)(smem + OFF_ALO);

    // ---- stage split weights with gate-row permutation ----
    for (int idx = tid; idx < 256*K; idx += 512){
        int m = idx / K, k = idx - m*K;
        int ww = m >> 4, r = m & 15;
        int jcell = 4*ww + ((r & 7) >> 1);
        int gate  = (r < 8) ? (r & 1) : 2 + (r & 1);
        int n = gate*64 + jcell;
        float v = 0.f;
        if (k < KIN)                          v = wih[n*KIN + k];
        else if (k >= HOFF && k < HOFF + H_)  v = whh[n*H_ + (k - HOFF)];
        __half hi = __float2half_rn(v);
        Ahi[m*STRD + k] = hi;
        Alo[m*STRD + k] = __float2half_rn(v - __half2float(hi));
    }
    // zero both X buffers
    for (int i = tid; i < 8704; i += 512) ((uint32_t*)smem)[i] = 0u;
    __syncthreads();

    // ---- A-hi fragments resident in registers ----
    uint32_t ahi[KT][4];
    const int arow = (w << 4) + (lane & 7) + (((lane >> 3) & 1) << 3);
    const uint32_t abh = smem_u32(Ahi) + (uint32_t)(arow * STRD) * 2u;
    const uint32_t abl = smem_u32(Alo) + (uint32_t)(arow * STRD) * 2u;
    #pragma unroll
    for (int kt = 0; kt < KT; kt++)
        ldsm4(ahi[kt], abh + (uint32_t)(kt*16 + ((lane >> 4) << 3)) * 2u);

    // per-thread roles
    const int gq  = lane >> 2, tig = lane & 3;
    const int sel = gq & 1;
    const int jc  = 4*w + (gq >> 1);
    const float bI = bih[jc]      + bhh[jc];
    const float bF = bih[64+jc]   + bhh[64+jc];
    const float bG = bih[128+jc]  + bhh[128+jc];
    const float bO = bih[192+jc]  + bhh[192+jc];
    const int colbase = (sel ? 16 : 0) + 2*tig;
    const int bn = ((lane >> 4) << 3) + (lane & 7);
    const int bk = ((lane >> 3) & 1) << 3;
    const int frow = tid >> 4, fc0 = (tid & 15) << 2;
    float cst[4] = {0.f, 0.f, 0.f, 0.f};

    float xr0=0.f, xr1=0.f, xr2=0.f, xr3=0.f;

    auto xpref = [&](int t){
        if (KIN == 64){
            const float4 q = *(const float4*)&in_seq[((size_t)t*B_ + row0 + (tid>>4))*64 + ((tid&15)<<2)];
            xr0=q.x; xr1=q.y; xr2=q.z; xr3=q.w;
        } else if (KIN == 32){
            const float2 q = *(const float2*)&in_seq[((size_t)t*B_ + row0 + (tid>>4))*32 + ((tid&15)<<1)];
            xr0=q.x; xr1=q.y;
        } else {
            if (tid < 32*KIN)
                xr0 = in_seq[((size_t)t*B_ + row0 + tid/KIN)*KIN + (tid - (tid/KIN)*KIN)];
        }
    };
    auto xstore = [&](char* bdst){
        __half* BhN = (__half*)bdst;
        __half* BlN = (__half*)(bdst + B_LOB);
        if (KIN == 64){
            int r = tid >> 4, c0 = (tid & 15) << 2;
            __half h0=__float2half_rn(xr0), h1=__float2half_rn(xr1);
            __half h2=__float2half_rn(xr2), h3=__float2half_rn(xr3);
            *(__half2*)&BhN[r*STRD + c0]     = __half2(h0,h1);
            *(__half2*)&BhN[r*STRD + c0 + 2] = __half2(h2,h3);
            *(__half2*)&BlN[r*STRD + c0]     =
                __half2(__float2half_rn(xr0-__half2float(h0)), __float2half_rn(xr1-__half2float(h1)));
            *(__half2*)&BlN[r*STRD + c0 + 2] =
                __half2(__float2half_rn(xr2-__half2float(h2)), __float2half_rn(xr3-__half2float(h3)));
        } else if (KIN == 32){
            int r = tid >> 4, c0 = (tid & 15) << 1;
            __half h0=__float2half_rn(xr0), h1=__float2half_rn(xr1);
            *(__half2*)&BhN[r*STRD + c0] = __half2(h0, h1);
            *(__half2*)&BlN[r*STRD + c0] =
                __half2(__float2half_rn(xr0-__half2float(h0)), __float2half_rn(xr1-__half2float(h1)));
        } else {
            if (tid < 32*KIN){
                int r = tid / KIN, k = tid - r*KIN;
                __half h0 = __float2half_rn(xr0);
                BhN[r*STRD + k] = h0;
                BlN[r*STRD + k] = __float2half_rn(xr0 - __half2float(h0));
            }
        }
    };
    auto mma12 = [&](float (&c)[4][4], const uint32_t* ah, const uint32_t* al,
                     const uint32_t* xh0, const uint32_t* xh1,
                     const uint32_t* xl0, const uint32_t* xl1){
        mma16816(c[0], ah, xh0[0], xh0[1]);
        mma16816(c[1], ah, xh0[2], xh0[3]);
        mma16816(c[2], ah, xh1[0], xh1[1]);
        mma16816(c[3], ah, xh1[2], xh1[3]);
        mma16816(c[0], ah, xl0[0], xl0[1]);
        mma16816(c[1], ah, xl0[2], xl0[3]);
        mma16816(c[2], ah, xl1[0], xl1[1]);
        mma16816(c[3], ah, xl1[2], xl1[3]);
        mma16816(c[0], al, xh0[0], xh0[1]);
        mma16816(c[1], al, xh0[2], xh0[3]);
        mma16816(c[2], al, xh1[0], xh1[1]);
        mma16816(c[3], al, xh1[2], xh1[3]);
    };
    auto xpart = [&](float (&cA)[4][4], uint32_t boff){
        #pragma unroll
        for (int nt = 0; nt < 4; nt++){ cA[nt][0]=0.f; cA[nt][1]=0.f; cA[nt][2]=0.f; cA[nt][3]=0.f; }
        const uint32_t h0 = sbase + boff + (uint32_t)(bn*STRD + bk)*2u;
        const uint32_t h1 = h0 + 16u*STRD*2u;
        const uint32_t l0 = h0 + B_LOB, l1 = h1 + B_LOB;
        #pragma unroll
        for (int kt = 0; kt < XT; kt++){
            const uint32_t ko = (uint32_t)kt * 32u;
            uint32_t xh0[4], xh1[4], xl0[4], xl1[4], alo[4];
            ldsm4(xh0, h0 + ko); ldsm4(xh1, h1 + ko);
            ldsm4(xl0, l0 + ko); ldsm4(xl1, l1 + ko);
            ldsm4(alo, abl + (uint32_t)(kt*16 + ((lane >> 4) << 3)) * 2u);
            mma12(cA, ahi[kt], alo, xh0, xh1, xl0, xl1);
        }
    };

    // ---- prime: x(0) -> buf0, xr <- x(1), c0 <- x-part(t=0) ----
    {
        __half* Bh = (__half*)(smem + OFF_B0);
        __half* Bl = (__half*)(smem + OFF_B0 + B_LOB);
        for (int idx = tid; idx < 32*KIN; idx += 512){
            int r = idx / KIN, k = idx - r*KIN;
            float v = in_seq[((size_t)row0 + r)*KIN + k];
            __half hi = __float2half_rn(v);
            Bh[r*STRD + k] = hi;
            Bl[r*STRD + k] = __float2half_rn(v - __half2float(hi));
        }
    }
    xpref(1);
    __syncthreads();
    float c0[4][4], c1[4][4];
    xpart(c0, OFF_B0);

    auto stepf = [&](int t, float (&cU)[4][4], float (&cA)[4][4]){
        const int p = t & 1;
        const uint32_t curoff = p ? OFF_B1 : OFF_B0;
        const uint32_t nxtoff = p ? OFF_B0 : OFF_B1;
        char* bnext = smem + nxtoff;
        float* hbW = (float*)(smem + (p ? OFF_HB1 : OFF_HB0));

        // stream ys(t-1) (overlaps h-part GEMM)
        if (ys && t > 0){
            const float* hbR = (const float*)(smem + (p ? OFF_HB0 : OFF_HB1));
            float4 v = *(const float4*)&hbR[frow*HBSTR + fc0];
            *(float4*)&ys[((size_t)(t-1)*B_ + row0 + frow)*H_ + fc0] = v;
        }

        // ---- h-part GEMM for step t ----
        {
            const uint32_t h0 = sbase + curoff + (uint32_t)(bn*STRD + bk)*2u;
            const uint32_t h1 = h0 + 16u*STRD*2u;
            const uint32_t l0 = h0 + B_LOB, l1 = h1 + B_LOB;
            #pragma unroll
            for (int kt = 0; kt < HT; kt++){
                const int kk = XT + kt;
                const uint32_t ko = (uint32_t)kk * 32u;
                uint32_t xh0[4], xh1[4], xl0[4], xl1[4], alo[4];
                ldsm4(xh0, h0 + ko); ldsm4(xh1, h1 + ko);
                ldsm4(xl0, l0 + ko); ldsm4(xl1, l1 + ko);
                ldsm4(alo, abl + (uint32_t)(kk*16 + ((lane >> 4) << 3)) * 2u);
                mma12(cU, ahi[kk], alo, xh0, xh1, xl0, xl1);
            }
        }

        // ---- lane^4 exchange of exactly the half the partner needs ----
        // send: sel? cU[u][q] (F/O rows, cols<16) : cU[u+2][q] (I/G rows, cols>=16)
        float xc2[2][4];
        #pragma unroll
        for (int u = 0; u < 2; u++)
            #pragma unroll
            for (int q = 0; q < 4; q++)
                xc2[u][q] = __shfl_xor_sync(0xffffffffu, sel ? cU[u][q] : cU[u+2][q], 4);

        // ---- publish x(t+1) to next buffer, then mid barrier ----
        if (t + 1 < S_) xstore(bnext);
        __syncthreads();

        // ---- issue x-part GEMM for t+1 (retires under the MUFU update below) ----
        if (t + 1 < S_) xpart(cA, nxtoff);
        if (t + 2 < S_) xpref(t + 2);

        // ---- update 4 cells ----
        __half* BhN = (__half*)bnext;
        __half* BlN = (__half*)(bnext + B_LOB);
        #pragma unroll
        for (int u = 0; u < 2; u++){
            #pragma unroll
            for (int pp = 0; pp < 2; pp++){
                float own0 = sel ? cU[u+2][pp]    : cU[u][pp];
                float own2 = sel ? cU[u+2][2+pp]  : cU[u][2+pp];
                float oth0 = xc2[u][pp];
                float oth2 = xc2[u][2+pp];
                float gi = (sel ? oth0 : own0) + bI;
                float gf = (sel ? own0 : oth0) + bF;
                float gg = (sel ? oth2 : own2) + bG;
                float go = (sel ? own2 : oth2) + bO;
                int li = u*2 + pp;
                float cc = sig_a(gf)*cst[li] + sig_a(gi)*tanh_(gg);
                cst[li] = cc;
                float h = sig_a(go)*tanh_(cc);
                int col = colbase + u*8 + pp;
                __half hh = __float2half_rn(h);
                BhN[col*STRD + HOFF + jc] = hh;
                BlN[col*STRD + HOFF + jc] = __float2half_rn(h - __half2float(hh));
                if (ys) hbW[col*HBSTR + jc] = h;
                if (hf && t == S_-1) hf[(row0 + col)*H_ + jc] = h;
            }
        }
        __syncthreads();
    };

    for (int t = 0; t < S_; t += 2){
        stepf(t,     c0, c1);
        stepf(t + 1, c1, c0);
    }

    // final ys flush (step S-1 wrote hb[(S-1)&1] = HB1)
    if (ys){
        const float* hbR = (const float*)(smem + OFF_HB1);
        float4 v = *(const float4*)&hbR[frow*HBSTR + fc0];
        *(float4*)&ys[((size_t)(S_-1)*B_ + row0 + frow)*H_ + fc0] = v;
    }
}

__global__ void __launch_bounds__(512, 1) lstm_l0(
    const float* __restrict__ c_wih, const float* __restrict__ c_whh,
    const float* __restrict__ c_bih, const float* __restrict__ c_bhh,
    const float* __restrict__ v_wih, const float* __restrict__ v_whh,
    const float* __restrict__ v_bih, const float* __restrict__ v_bhh)
{
    extern __shared__ char smem[];
    if (blockIdx.x < 64)
        lstm_stream<2, 4, CC>(smem, g_convout, g_ys_cnn, nullptr, blockIdx.x*32,
                              c_wih, c_whh, c_bih, c_bhh);
    else
        lstm_stream<1, 4, DIN>(smem, g_xT, g_ys_vq, nullptr, (blockIdx.x-64)*32,
                               v_wih, v_whh, v_bih, v_bhh);
}

__global__ void __launch_bounds__(512, 1) lstm_l1(
    const float* __restrict__ c_wih, const float* __restrict__ c_whh,
    const float* __restrict__ c_bih, const float* __restrict__ c_bhh,
    const float* __restrict__ v_wih, const float* __restrict__ v_whh,
    const float* __restrict__ v_bih, const float* __restrict__ v_bhh)
{
    extern __shared__ char smem[];
    if (blockIdx.x < 64)
        lstm_stream<4, 4, H_>(smem, g_ys_cnn, nullptr, g_cnn_feat, blockIdx.x*32,
                              c_wih, c_whh, c_bih, c_bhh);
    else
        lstm_stream<4, 4, H_>(smem, g_ys_vq, nullptr, g_vq_hid, (blockIdx.x-64)*32,
                              v_wih, v_whh, v_bih, v_bhh);
}

// ---------------- VQ epilogue ----------------
__global__ void zero_k(){
    int t = threadIdx.x;
    if (t < NEMB) g_counts[t] = 0;
    if (t == 0)   g_sqsum = 0.f;
}

__global__ void vq_final(const float* __restrict__ proj_w, const float* __restrict__ proj_b,
                         const float* __restrict__ codebook, float* __restrict__ out)
{
    __shared__ float pw[EDIM*H_];
    __shared__ float pb[EDIM];
    __shared__ float cb[NEMB*EDIM];
    __shared__ float cn2[NEMB];
    __shared__ float red[256];
    int tid = threadIdx.x;
    for (int i = tid; i < EDIM*H_;   i += 256) pw[i] = proj_w[i];
    for (int i = tid; i < NEMB*EDIM; i += 256) cb[i] = codebook[i];
    if (tid < EDIM) pb[tid] = proj_b[tid];
    __syncthreads();
    if (tid < NEMB){
        float s = 0.f;
        #pragma unroll
        for (int e = 0; e < EDIM; e++){ float v = cb[tid*EDIM + e]; s = fmaf(v, v, s); }
        cn2[tid] = s;
    }
    __syncthreads();

    int b = blockIdx.x*256 + tid;
    float h[H_];
    const float4* hp = (const float4*)&g_vq_hid[b*H_];
    #pragma unroll
    for (int i = 0; i < H_/4; i++){
        float4 v = hp[i]; h[4*i] = v.x; h[4*i+1] = v.y; h[4*i+2] = v.z; h[4*i+3] = v.w;
    }
    float p[EDIM]; float p2 = 0.f;
    #pragma unroll
    for (int e = 0; e < EDIM; e++){
        float a = pb[e];
        #pragma unroll
        for (int d = 0; d < H_; d++) a = fmaf(pw[e*H_ + d], h[d], a);
        p[e] = a; p2 = fmaf(a, a, p2);
    }
    int best = 0; float dmin = 3.4e38f;
    #pragma unroll 4
    for (int n = 0; n < NEMB; n++){
        float dot = 0.f;
        #pragma unroll
        for (int e = 0; e < EDIM; e++) dot = fmaf(cb[n*EDIM + e], p[e], dot);
        float d = p2 + cn2[n] - 2.f*dot;
        if (d < dmin){ dmin = d; best = n; }
    }
    float rs = 0.f;
    #pragma unroll
    for (int e = 0; e < EDIM; e++){ float r = cb[best*EDIM + e] - p[e]; rs = fmaf(r, r, rs); }
    red[tid] = rs;
    atomicAdd(&g_counts[best], 1);

    const float* cf = &g_cnn_feat[b*H_];
    float* o0 = out + (size_t)b*96;
    float* o1 = out + (size_t)B_*96 + (size_t)b*96;
    #pragma unroll
    for (int jj = 0; jj < H_; jj++){ float v = cf[jj]; o0[jj] = v; o1[jj] = v; }
    #pragma unroll
    for (int e = 0; e < EDIM; e++){ float v = cb[best*EDIM + e]; o0[H_+e] = v; o1[H_+e] = v; }

    __syncthreads();
    for (int st = 128; st > 0; st >>= 1){
        if (tid < st) red[tid] += red[tid + st];
        __syncthreads();
    }
    if (tid == 0) atomicAdd(&g_sqsum, red[0]);
}

__global__ void finalize_k(float* __restrict__ out){
    if (threadIdx.x == 0){
        float msq = g_sqsum / (float)(B_*EDIM);
        out[(size_t)2*B_*96]     = msq + 0.01f * msq;
        float ent = 0.f;
        for (int n = 0; n < NEMB; n++){
            float ap = (float)g_counts[n] / (float)B_;
            ent += ap * logf(ap + 1e-10f);
        }
        out[(size_t)2*B_*96 + 1] = expf(-ent);
    }
}

// ---------------- launch ----------------
extern "C" void kernel_launch(void* const* d_in, const int* in_sizes, int n_in,
                              void* d_out, int out_size)
{
    const float* x       = (const float*)d_in[0];
    const float* conv_w  = (const float*)d_in[1];
    const float* conv_b  = (const float*)d_in[2];
    const float* bn_g    = (const float*)d_in[3];
    const float* bn_b    = (const float*)d_in[4];
    const float* bn_m    = (const float*)d_in[5];
    const float* bn_v    = (const float*)d_in[6];
    const float* c0_wih  = (const float*)d_in[7];
    const float* c0_whh  = (const float*)d_in[8];
    const float* c0_bih  = (const float*)d_in[9];
    const float* c0_bhh  = (const float*)d_in[10];
    const float* c1_wih  = (const float*)d_in[11];
    const float* c1_whh  = (const float*)d_in[12];
    const float* c1_bih  = (const float*)d_in[13];
    const float* c1_bhh  = (const float*)d_in[14];
    const float* v0_wih  = (const float*)d_in[15];
    const float* v0_whh  = (const float*)d_in[16];
    const float* v0_bih  = (const float*)d_in[17];
    const float* v0_bhh  = (const float*)d_in[18];
    const float* v1_wih  = (const float*)d_in[19];
    const float* v1_whh  = (const float*)d_in[20];
    const float* v1_bih  = (const float*)d_in[21];
    const float* v1_bhh  = (const float*)d_in[22];
    const float* proj_w  = (const float*)d_in[23];
    const float* proj_b  = (const float*)d_in[24];
    const float* codebook= (const float*)d_in[25];
    float* out = (float*)d_out;

    cudaFuncSetAttribute(lstm_l0, cudaFuncAttributeMaxDynamicSharedMemorySize, SMEM_TOT);
    cudaFuncSetAttribute(lstm_l1, cudaFuncAttributeMaxDynamicSharedMemorySize, SMEM_TOT);

    prep_kernel<<<(B_*S_)/256, 256>>>(x, conv_w, conv_b, bn_g, bn_b, bn_m, bn_v);
    zero_k<<<1, 64>>>();
    lstm_l0<<<128, 512, SMEM_TOT>>>(c0_wih, c0_whh, c0_bih, c0_bhh,
                                    v0_wih, v0_whh, v0_bih, v0_bhh);
    lstm_l1<<<128, 512, SMEM_TOT>>>(c1_wih, c1_whh, c1_bih, c1_bhh,
                                    v1_wih, v1_whh, v1_bih, v1_bhh);
    vq_final<<<B_/256, 256>>>(proj_w, proj_b, codebook, out);
    finalize_k<<<1, 64>>>(out);
}